// round 12
// baseline (speedup 1.0000x reference)
#include <cuda_runtime.h>
#include <cuda_bf16.h>
#include <cstdint>

// ---------------------------------------------------------------------------
// RelativeMultiHeadAttn (Transformer-XL style) forward.
//
// qkv = x @ Wqkv via tcgen05 bf16 split-precision GEMM (K concat trick):
//   A2 = [Xhi | Xlo | Xhi]  (4096 x 3072 bf16, K-major)
//   B2 = [Whi | Whi | Wlo]^T (3072 x 3072 bf16, K-major)
//   qkv = A2 @ B2^T  accumulated fp32 in TMEM  ==  x@W up to ~2^-18 residual.
// tcgen05 / f32x2 bodies guarded for the sm_103a arch-specific pass; the
// plain compute_103 pass compiles scalar fp32 fallbacks.
//
// score: 128x64 tiles, blocked 8x4/thread, scalar FMA + LDS.128 (the R11
// f32x2 experiment regressed: register-pair pressure). Band trick:
//   BD_shift[i,j] = (q_i + r_w) . R[:, L + j - i]
//   E_term[i,j]   = k_j . R[:, L + i - j]
// av: softmax + PV with packed f32x2 FMAs over d-pairs (layout-natural).
// ---------------------------------------------------------------------------

namespace {
constexpr int BATCH = 8;
constexpr int NH    = 16;
constexpr int SEQ   = 512;
constexpr int DM    = 1024;
constexpr int HD    = 64;
constexpr int P2    = 2 * SEQ;      // 1024
constexpr int BH    = BATCH * NH;   // 128
constexpr int QKV_N = 3 * DM;       // 3072
constexpr int MROWS = BATCH * SEQ;  // 4096
constexpr int KTOT  = 3 * DM;       // 3072 (split-K concat)
constexpr int CH    = 64;           // K chunk (one SW128 atom column of bf16)
constexpr int NCH   = KTOT / CH;    // 48
}

// scratch (static device globals: allowed; no dynamic allocation)
__device__ float         g_qkv[(size_t)MROWS * QKV_N];    // 50 MB fp32
__device__ __nv_bfloat16 g_A2[(size_t)MROWS * KTOT];      // 25 MB
__device__ __nv_bfloat16 g_B2[(size_t)QKV_N * KTOT];      // 19 MB

// Feature gate: true only in the sm_103a (arch-specific) device pass.
#ifndef __CUDA_ARCH_SPECIFIC__
#define __CUDA_ARCH_SPECIFIC__ 0
#endif
#if !defined(__CUDA_ARCH__) || defined(__CUDA_ARCH_FEAT_SM103_ALL) || \
    (__CUDA_ARCH_SPECIFIC__ == 1030)
#define HAS_TCGEN05 1
#else
#define HAS_TCGEN05 0
#endif

typedef unsigned long long ull;

// packed fp32x2 FMA: d.lo += a.lo*b.lo ; d.hi += a.hi*b.hi
#if HAS_TCGEN05
__device__ __forceinline__ void ffma2(ull& d, ull a, ull b) {
  asm("fma.rn.f32x2 %0, %1, %2, %0;" : "+l"(d) : "l"(a), "l"(b));
}
#else
__device__ __forceinline__ void ffma2(ull& d, ull a, ull b) {
  float dl = __uint_as_float((uint32_t)d),  dh = __uint_as_float((uint32_t)(d >> 32));
  float al = __uint_as_float((uint32_t)a),  ah = __uint_as_float((uint32_t)(a >> 32));
  float bl = __uint_as_float((uint32_t)b),  bh = __uint_as_float((uint32_t)(b >> 32));
  dl = fmaf(al, bl, dl);
  dh = fmaf(ah, bh, dh);
  d = (ull)__float_as_uint(dl) | ((ull)__float_as_uint(dh) << 32);
}
#endif

// ===========================================================================
// minimal sm_103a PTX helpers
// ===========================================================================
__device__ __forceinline__ uint32_t smem_u32(const void* p) {
  uint32_t a;
  asm("{ .reg .u64 t; cvta.to.shared.u64 t, %1; cvt.u32.u64 %0, t; }"
      : "=r"(a) : "l"(p));
  return a;
}
#if HAS_TCGEN05
__device__ __forceinline__ uint32_t elect_one() {
  uint32_t pred;
  asm volatile("{\n\t.reg .pred p;\n\telect.sync _|p, 0xFFFFFFFF;\n\t"
               "selp.b32 %0, 1, 0, p;\n\t}" : "=r"(pred));
  return pred;
}
__device__ __forceinline__ void mbar_init(uint32_t mbar, uint32_t cnt) {
  asm volatile("mbarrier.init.shared.b64 [%0], %1;" :: "r"(mbar), "r"(cnt) : "memory");
}
__device__ __forceinline__ void mbar_wait(uint32_t mbar, uint32_t parity) {
  asm volatile(
      "{\n\t.reg .pred P;\n\t"
      "WL_%=:\n\t"
      "mbarrier.try_wait.parity.acquire.cta.shared::cta.b64 P, [%0], %1, 0x989680;\n\t"
      "@P bra.uni WD_%=;\n\t"
      "bra.uni WL_%=;\n\t"
      "WD_%=:\n\t}"
      :: "r"(mbar), "r"(parity) : "memory");
}
__device__ __forceinline__ void tmem_alloc(uint32_t smem_dst, uint32_t ncols) {
  asm volatile("tcgen05.alloc.cta_group::1.sync.aligned.shared::cta.b32 [%0], %1;"
               :: "r"(smem_dst), "r"(ncols) : "memory");
}
__device__ __forceinline__ void tmem_relinq() {
  asm volatile("tcgen05.relinquish_alloc_permit.cta_group::1.sync.aligned;");
}
__device__ __forceinline__ void tmem_dealloc(uint32_t tmem, uint32_t ncols) {
  asm volatile("tcgen05.dealloc.cta_group::1.sync.aligned.b32 %0, %1;"
               :: "r"(tmem), "r"(ncols));
}
__device__ __forceinline__ void tcommit(uint32_t mbar) {
  asm volatile(
      "tcgen05.commit.cta_group::1.mbarrier::arrive::one.shared::cluster.b64 [%0];"
      :: "r"(mbar) : "memory");
}
__device__ __forceinline__ void fence_async_shared() {
  asm volatile("fence.proxy.async.shared::cta;" ::: "memory");
}
__device__ __forceinline__ void tfence_after() {
  asm volatile("tcgen05.fence::after_thread_sync;" ::: "memory");
}
__device__ __forceinline__ void mma_f16_ss(uint32_t d, uint64_t ad, uint64_t bd,
                                           uint32_t idesc, uint32_t en) {
  asm volatile(
      "{\n\t.reg .pred p;\n\tsetp.ne.u32 p, %5, 0;\n\t"
      "tcgen05.mma.cta_group::1.kind::f16 [%0], %1, %2, %3, {%4, %4, %4, %4}, p;\n\t}"
      :: "r"(d), "l"(ad), "l"(bd), "r"(idesc), "r"(0u), "r"(en) : "memory");
}
#define TC_LD_X32(r, addr)                                                      \
  asm volatile(                                                                 \
      "tcgen05.ld.sync.aligned.32x32b.x32.b32 "                                 \
      "{%0,%1,%2,%3,%4,%5,%6,%7,%8,%9,%10,%11,%12,%13,%14,%15,"                \
      "%16,%17,%18,%19,%20,%21,%22,%23,%24,%25,%26,%27,%28,%29,%30,%31}, [%32];" \
      : "=r"((r)[0]), "=r"((r)[1]), "=r"((r)[2]), "=r"((r)[3]),                 \
        "=r"((r)[4]), "=r"((r)[5]), "=r"((r)[6]), "=r"((r)[7]),                 \
        "=r"((r)[8]), "=r"((r)[9]), "=r"((r)[10]), "=r"((r)[11]),               \
        "=r"((r)[12]), "=r"((r)[13]), "=r"((r)[14]), "=r"((r)[15]),             \
        "=r"((r)[16]), "=r"((r)[17]), "=r"((r)[18]), "=r"((r)[19]),             \
        "=r"((r)[20]), "=r"((r)[21]), "=r"((r)[22]), "=r"((r)[23]),             \
        "=r"((r)[24]), "=r"((r)[25]), "=r"((r)[26]), "=r"((r)[27]),             \
        "=r"((r)[28]), "=r"((r)[29]), "=r"((r)[30]), "=r"((r)[31])              \
      : "r"(addr))
__device__ __forceinline__ void tc_wait_ld() {
  asm volatile("tcgen05.wait::ld.sync.aligned;" ::: "memory");
}
// SW128 K-major SMEM descriptor (LBO=1, SBO=64, version=1, layout=2)
__device__ __forceinline__ uint64_t smem_desc_sw128(uint32_t addr) {
  const uint64_t base = (uint64_t(2) << 61) | (uint64_t(1) << 46) |
                        (uint64_t(64) << 32) | (uint64_t(1) << 16);
  return base | ((uint64_t)(addr >> 4) & 0x3FFF);
}
#endif  // HAS_TCGEN05

// idesc: fp32 accum, bf16 x bf16, M=128, N=128
namespace {
constexpr uint32_t IDESC =
    (1u << 4) | (1u << 7) | (1u << 10) | ((128u / 8) << 17) | ((128u / 16) << 24);
}

// ===========================================================================
// Conversion kernels: fp32 -> split bf16 (hi/lo), B transposed to K-major
// ===========================================================================
__global__ __launch_bounds__(256) void k_convA(const float* __restrict__ X) {
  size_t i = (size_t)blockIdx.x * 256 + threadIdx.x;  // quad index
  float4 v = ((const float4*)X)[i];
  size_t m = i >> 8;
  size_t q = (i & 255) * 4;

  __nv_bfloat162 h01 = __floats2bfloat162_rn(v.x, v.y);
  __nv_bfloat162 h23 = __floats2bfloat162_rn(v.z, v.w);
  float lx = v.x - __bfloat162float(h01.x);
  float ly = v.y - __bfloat162float(h01.y);
  float lz = v.z - __bfloat162float(h23.x);
  float lw = v.w - __bfloat162float(h23.y);
  __nv_bfloat162 l01 = __floats2bfloat162_rn(lx, ly);
  __nv_bfloat162 l23 = __floats2bfloat162_rn(lz, lw);

  uint2 uh, ul;
  uh.x = *(uint32_t*)&h01; uh.y = *(uint32_t*)&h23;
  ul.x = *(uint32_t*)&l01; ul.y = *(uint32_t*)&l23;

  __nv_bfloat16* row = g_A2 + m * KTOT;
  *(uint2*)(row + q)          = uh;
  *(uint2*)(row + DM + q)     = ul;
  *(uint2*)(row + 2 * DM + q) = uh;
}

__global__ __launch_bounds__(256) void k_convB(const float* __restrict__ W) {
  __shared__ float tile[32][33];
  const int n0 = blockIdx.x * 32;
  const int k0 = blockIdx.y * 32;
  const int tid = threadIdx.x;
#pragma unroll
  for (int it = 0; it < 4; it++) {
    int e = tid + it * 256;
    int kk = e >> 5, nn = e & 31;
    tile[kk][nn] = W[(size_t)(k0 + kk) * QKV_N + n0 + nn];
  }
  __syncthreads();
#pragma unroll
  for (int it = 0; it < 4; it++) {
    int e = tid + it * 256;
    int nn = e >> 5, kk = e & 31;
    float x = tile[kk][nn];
    __nv_bfloat16 hi = __float2bfloat16_rn(x);
    __nv_bfloat16 lo = __float2bfloat16_rn(x - __bfloat162float(hi));
    __nv_bfloat16* row = g_B2 + (size_t)(n0 + nn) * KTOT;
    row[k0 + kk]          = hi;
    row[DM + k0 + kk]     = hi;
    row[2 * DM + k0 + kk] = lo;
  }
}

// ===========================================================================
// Kernel: qkv = A2 @ B2^T via tcgen05 (unchanged from round 7)
// ===========================================================================
namespace {
constexpr int QSMEM = 1024 + 4 * 16384;
}

__global__ __launch_bounds__(256) void k_qkv_mma(const float* __restrict__ X,
                                                 const float* __restrict__ W) {
#if HAS_TCGEN05
  extern __shared__ char smem[];
  const uint32_t sb = smem_u32(smem);
  const uint32_t TPTR  = sb;
  const uint32_t MBAR0 = sb + 16;
  const uint32_t MBAR1 = sb + 24;
  const uint32_t STAGE = sb + 1024;

  const int tid = threadIdx.x;
  const int wid = tid >> 5;

  if (wid == 0) tmem_alloc(TPTR, 128);
  if (tid == 0) { mbar_init(MBAR0, 1); mbar_init(MBAR1, 1); }
  __syncthreads();
  uint32_t tmem;
  asm volatile("ld.shared.b32 %0, [%1];" : "=r"(tmem) : "r"(TPTR));
  if (wid == 0) tmem_relinq();

  const int m0 = blockIdx.y * 128;
  const int n0 = blockIdx.x * 128;
  const __nv_bfloat16* Ag = g_A2 + (size_t)m0 * KTOT;
  const __nv_bfloat16* Bg = g_B2 + (size_t)n0 * KTOT;

  const int row = tid >> 1;
  const int sg0 = (tid & 1) * 4;

  uint32_t ph0 = 0, ph1 = 0;
  for (int t = 0; t < NCH; t++) {
    const int p = t & 1;
    const uint32_t Abase = STAGE + p * 32768;
    const uint32_t Bbase = Abase + 16384;
    if (t >= 2) {
      if (p == 0) { mbar_wait(MBAR0, ph0); ph0 ^= 1; }
      else        { mbar_wait(MBAR1, ph1); ph1 ^= 1; }
    }
    const int kc = t * CH;
    uint4 av[4], bv[4];
    const char* arow = (const char*)(Ag + (size_t)row * KTOT + kc);
    const char* brow = (const char*)(Bg + (size_t)row * KTOT + kc);
#pragma unroll
    for (int s = 0; s < 4; s++) {
      av[s] = *(const uint4*)(arow + (sg0 + s) * 16);
      bv[s] = *(const uint4*)(brow + (sg0 + s) * 16);
    }
#pragma unroll
    for (int s = 0; s < 4; s++) {
      uint32_t off = row * 128 + (sg0 + s) * 16;
      uint32_t sw = off ^ ((off >> 3) & 0x70);
      *(uint4*)(smem + (Abase - sb) + sw) = av[s];
      *(uint4*)(smem + (Bbase - sb) + sw) = bv[s];
    }
    __syncthreads();
    if (wid == 0) {
      if (elect_one()) {
        fence_async_shared();
        uint64_t ad = smem_desc_sw128(Abase);
        uint64_t bd = smem_desc_sw128(Bbase);
#pragma unroll
        for (int k = 0; k < 4; k++)
          mma_f16_ss(tmem, ad + k * 2, bd + k * 2, IDESC, (t > 0 || k > 0) ? 1u : 0u);
        tcommit(p == 0 ? MBAR0 : MBAR1);
      }
    }
  }
  mbar_wait(MBAR1, ph1);
  tfence_after();

  if (wid < 4) {
    const int lid = tid & 31;
    const int orow = m0 + wid * 32 + lid;
#pragma unroll
    for (int cb = 0; cb < 128; cb += 32) {
      uint32_t d[32];
      TC_LD_X32(d, tmem + cb);
      tc_wait_ld();
      float* dst = g_qkv + (size_t)orow * QKV_N + n0 + cb;
#pragma unroll
      for (int c = 0; c < 32; c += 4)
        *(float4*)(dst + c) = make_float4(__uint_as_float(d[c]),
                                          __uint_as_float(d[c + 1]),
                                          __uint_as_float(d[c + 2]),
                                          __uint_as_float(d[c + 3]));
    }
  }
  __syncthreads();
  if (wid == 0) tmem_dealloc(tmem, 128);

#else  // ------------- FFMA fallback (non-sm_103a pass; still correct) -------
  extern __shared__ char smemraw[];
  float* sA = (float*)smemraw;
  float* sB = sA + 16 * 128;
  const int K = DM, N = QKV_N;
  const int tid = threadIdx.x;
  const int tx = tid & 15, ty = tid >> 4;
  const int row0 = blockIdx.y * 128;
  const int col0 = blockIdx.x * 128;

  float acc[8][8];
#pragma unroll
  for (int r = 0; r < 8; r++)
#pragma unroll
    for (int c = 0; c < 8; c++) acc[r][c] = 0.f;

  for (int kk = 0; kk < K; kk += 16) {
#pragma unroll
    for (int it = 0; it < 2; it++) {
      int e = tid + it * 256;
      int ar = e >> 2;
      int ac = (e & 3) * 4;
      float4 a4 = *(const float4*)(X + (size_t)(row0 + ar) * K + kk + ac);
      sA[(ac + 0) * 128 + ar] = a4.x;
      sA[(ac + 1) * 128 + ar] = a4.y;
      sA[(ac + 2) * 128 + ar] = a4.z;
      sA[(ac + 3) * 128 + ar] = a4.w;
    }
#pragma unroll
    for (int it = 0; it < 2; it++) {
      int e = tid + it * 256;
      int br = e >> 5;
      int bc = (e & 31) * 4;
      *(float4*)&sB[br * 128 + bc] = *(const float4*)(W + (size_t)(kk + br) * N + col0 + bc);
    }
    __syncthreads();
#pragma unroll
    for (int k = 0; k < 16; k++) {
      float ar[8], bc[8];
      *(float4*)&ar[0] = *(float4*)&sA[k * 128 + ty * 8];
      *(float4*)&ar[4] = *(float4*)&sA[k * 128 + ty * 8 + 4];
      *(float4*)&bc[0] = *(float4*)&sB[k * 128 + tx * 8];
      *(float4*)&bc[4] = *(float4*)&sB[k * 128 + tx * 8 + 4];
#pragma unroll
      for (int r = 0; r < 8; r++)
#pragma unroll
        for (int c = 0; c < 8; c++) acc[r][c] += ar[r] * bc[c];
    }
    __syncthreads();
  }
#pragma unroll
  for (int r = 0; r < 8; r++) {
    float* dst = g_qkv + (size_t)(row0 + ty * 8 + r) * QKV_N + col0 + tx * 8;
    *(float4*)dst       = make_float4(acc[r][0], acc[r][1], acc[r][2], acc[r][3]);
    *(float4*)(dst + 4) = make_float4(acc[r][4], acc[r][5], acc[r][6], acc[r][7]);
  }
#endif
}

// ===========================================================================
// Kernel: fused score. 128x64 tile, 256 threads, blocked 8x4 per thread,
// scalar FMA with LDS.128 operands (144B LDS per 32 outputs per d).
// Bands are 191 wide (row span 128), d-chunked (DCH=16).
// attn_score = (AC + BD + E)/8 + prev -> prev_out
// ===========================================================================
namespace {
constexpr int DCH     = 16;
constexpr int BSTR    = 192;   // band row stride (191 used)
constexpr int SC_SMEM = (64 * 128 + 64 * 64 + 2 * DCH * BSTR) * 4;  // 73728 B
}

__global__ __launch_bounds__(256) void k_score(const float* __restrict__ rrb,
                                               const float* __restrict__ rwb,
                                               const float* __restrict__ relpos,
                                               const float* __restrict__ prev,
                                               const int* __restrict__ skip,
                                               float* __restrict__ prev_out) {
  extern __shared__ float smemf[];
  float* sQT = smemf;               // [64 d][128 r]
  float* sKT = sQT + 64 * 128;      // [64 d][64 c]
  float* sRq = sKT + 64 * 64;       // [DCH][BSTR] band chunk for BD (191 used)
  float* sRe = sRq + DCH * BSTR;    // [DCH][BSTR] band chunk for E
  __shared__ float cK[64];          // rrb . k_j
  __shared__ float cRq[BSTR];       // rwb . R_t (191 used), accumulated

  const int bh = blockIdx.z;
  const int b = bh >> 4, h = bh & 15;
  const int tid = threadIdx.x;
  const int tx = tid & 15, ty = tid >> 4;
  const int i0 = blockIdx.y * 128;
  const int j0 = blockIdx.x * 64;

  const float* Qb = g_qkv + (size_t)(b * SEQ) * QKV_N + h * HD;
  const float* Kb = Qb + DM;

  // load Q tile (128 rows) transposed into smem (d-major)
#pragma unroll
  for (int it = 0; it < 8; it++) {
    int e = tid + it * 256;       // 128 rows x 16 float4
    int r = e & 127;
    int c = (e >> 7) * 4;
    float4 q4 = *(const float4*)(Qb + (size_t)(i0 + r) * QKV_N + c);
    sQT[(c + 0) * 128 + r] = q4.x;
    sQT[(c + 1) * 128 + r] = q4.y;
    sQT[(c + 2) * 128 + r] = q4.z;
    sQT[(c + 3) * 128 + r] = q4.w;
  }
  // load K tile (64 cols) transposed
#pragma unroll
  for (int it = 0; it < 4; it++) {
    int e = tid + it * 256;       // 64 rows x 16 float4
    int r = e & 63;
    int c = (e >> 6) * 4;
    float4 k4 = *(const float4*)(Kb + (size_t)(j0 + r) * QKV_N + c);
    sKT[(c + 0) * 64 + r] = k4.x;
    sKT[(c + 1) * 64 + r] = k4.y;
    sKT[(c + 2) * 64 + r] = k4.z;
    sKT[(c + 3) * 64 + r] = k4.w;
  }
  if (tid < BSTR) cRq[tid] = 0.f;
  __syncthreads();

  // rank-1 correction cK (needs full-K sKT)
  if (tid < 64) {
    float s = 0.f;
#pragma unroll
    for (int d = 0; d < 64; d++) s += rrb[h * HD + d] * sKT[d * 64 + tid];
    cK[tid] = s;
  }

  float acc[8][4];
#pragma unroll
  for (int r = 0; r < 8; r++)
#pragma unroll
    for (int c = 0; c < 4; c++) acc[r][c] = 0.f;

  // blocked tile: rows i0 + ty*8 + r (r<8), cols j0 + tx*4 + c (c<4)
  // BD band x = (j_local - i_local) + 127; thread base xq0 = tx*4 - ty*8 + 120
  //   (x for (r,c) = xq0 + 7 + c - r; reads xq0..xq0+10, 16B-aligned base)
  // E  band x = (i_local - j_local) + 63; thread base xe0 = ty*8 - tx*4 + 60
  //   (x for (r,c) = xe0 + 3 + r - c; reads xe0..xe0+10)
  const int xq0 = tx * 4 - ty * 8 + 120;   // in [0, 180]
  const int xe0 = ty * 8 - tx * 4 + 60;    // in [0, 180]
  const int q0g = SEQ + (j0 - i0) - 127;   // global band starts, within [1,1023]
  const int u0g = SEQ + (i0 - j0) - 63;

  for (int chk = 0; chk < 64 / DCH; chk++) {
    const int d0 = chk * DCH;
    // fill band chunks (191 of BSTR used)
    for (int e = tid; e < DCH * BSTR; e += 256) {
      int dl = e / BSTR, x = e - dl * BSTR;
      if (x < 191) {
        sRq[dl * BSTR + x] = relpos[(size_t)(d0 + dl) * P2 + q0g + x];
        sRe[dl * BSTR + x] = relpos[(size_t)(d0 + dl) * P2 + u0g + x];
      }
    }
    __syncthreads();

    // accumulate cRq partial for this chunk
    if (tid < 191) {
      float s = 0.f;
#pragma unroll
      for (int dl = 0; dl < DCH; dl++)
        s += rwb[h * HD + d0 + dl] * sRq[dl * BSTR + tid];
      cRq[tid] += s;
    }

#pragma unroll
    for (int dl = 0; dl < DCH; dl++) {
      const int d = d0 + dl;
      float a[8], bb[4], rq[12], re[12];
      *(float4*)&a[0]  = *(float4*)&sQT[d * 128 + ty * 8];
      *(float4*)&a[4]  = *(float4*)&sQT[d * 128 + ty * 8 + 4];
      *(float4*)&bb[0] = *(float4*)&sKT[d * 64 + tx * 4];
      *(float4*)&rq[0] = *(float4*)&sRq[dl * BSTR + xq0];
      *(float4*)&rq[4] = *(float4*)&sRq[dl * BSTR + xq0 + 4];
      *(float4*)&rq[8] = *(float4*)&sRq[dl * BSTR + xq0 + 8];
      *(float4*)&re[0] = *(float4*)&sRe[dl * BSTR + xe0];
      *(float4*)&re[4] = *(float4*)&sRe[dl * BSTR + xe0 + 4];
      *(float4*)&re[8] = *(float4*)&sRe[dl * BSTR + xe0 + 8];
#pragma unroll
      for (int r = 0; r < 8; r++)
#pragma unroll
        for (int c = 0; c < 4; c++)
          acc[r][c] += a[r] * bb[c] + a[r] * rq[c - r + 7] + bb[c] * re[r - c + 3];
    }
    __syncthreads();
  }

  const int sk = *skip;
  const float* prevb = prev + (size_t)bh * SEQ * SEQ;
  float* outb = prev_out + (size_t)bh * SEQ * SEQ;

#pragma unroll
  for (int r = 0; r < 8; r++) {
    const int i = i0 + ty * 8 + r;
    const int j = j0 + tx * 4;
    float4 p = make_float4(0.f, 0.f, 0.f, 0.f);
    if (sk) p = *(const float4*)(prevb + (size_t)i * SEQ + j);
    float4 o;
    o.x = (acc[r][0] + cK[tx * 4 + 0] + cRq[xq0 + 7 + 0 - r]) * 0.125f + p.x;
    o.y = (acc[r][1] + cK[tx * 4 + 1] + cRq[xq0 + 7 + 1 - r]) * 0.125f + p.y;
    o.z = (acc[r][2] + cK[tx * 4 + 2] + cRq[xq0 + 7 + 2 - r]) * 0.125f + p.z;
    o.w = (acc[r][3] + cK[tx * 4 + 3] + cRq[xq0 + 7 + 3 - r]) * 0.125f + p.w;
    *(float4*)(outb + (size_t)i * SEQ + j) = o;
  }
}

// ===========================================================================
// Kernel: out = softmax(S) @ V. 64 rows/block, 4x4 tile.
// sm_103a path: packed f32x2 FMAs over d-pairs, V stored d-interleaved.
// (unchanged from round 10)
// ===========================================================================
namespace {
constexpr int ROWS_AV   = 64;
constexpr int SS_STRIDE = 516;
constexpr int SMEM_AV   = (ROWS_AV * SS_STRIDE + 64 * 64) * 4;  // 148480 B
}

__global__ __launch_bounds__(256) void k_av(const float* __restrict__ Sglob,
                                            float* __restrict__ Out) {
  extern __shared__ float smemf[];
  float* sS = smemf;
  float* sV = smemf + ROWS_AV * SS_STRIDE;   // f32x2 path: [32 kp][64 c][2]
  __shared__ float sSum[ROWS_AV];

  const int bh = blockIdx.y;
  const int b = bh >> 4, h = bh & 15;
  const int row0 = blockIdx.x * ROWS_AV;
  const int tid = threadIdx.x;
  const int tx = tid & 15, ty = tid >> 4;
  const float* Sb = Sglob + ((size_t)bh * SEQ + row0) * SEQ;

#pragma unroll
  for (int it = 0; it < 32; it++) {
    int e = tid + it * 256;
    int r = e >> 7;
    int c = (e & 127) * 4;
    *(float4*)&sS[r * SS_STRIDE + c] = *(const float4*)(Sb + (size_t)r * SEQ + c);
  }
  __syncthreads();

  {
    const int warp = tid >> 5, lane = tid & 31;
#pragma unroll
    for (int rr = 0; rr < 8; rr++) {
      int row = warp * 8 + rr;
      float* srow = sS + row * SS_STRIDE;
      float mx = -1e30f;
      for (int c = lane; c < SEQ; c += 32) mx = fmaxf(mx, srow[c]);
#pragma unroll
      for (int o = 16; o > 0; o >>= 1) mx = fmaxf(mx, __shfl_xor_sync(0xffffffffu, mx, o));
      float sum = 0.f;
      for (int c = lane; c < SEQ; c += 32) {
        float p = __expf(srow[c] - mx);
        srow[c] = p;
        sum += p;
      }
#pragma unroll
      for (int o = 16; o > 0; o >>= 1) sum += __shfl_xor_sync(0xffffffffu, sum, o);
      if (lane == 0) sSum[row] = sum;
    }
  }

  const float* Vb = g_qkv + (size_t)(b * SEQ) * QKV_N + 2 * DM + h * HD;

#if HAS_TCGEN05
  // ---- packed f32x2 PV: accumulate even-d in lane0, odd-d in lane1 ----
  ull acc2[4][4];
#pragma unroll
  for (int r = 0; r < 4; r++)
#pragma unroll
    for (int c = 0; c < 4; c++) acc2[r][c] = 0ull;

  for (int kc = 0; kc < SEQ; kc += 64) {
    __syncthreads();
    // fill V interleaved: sV[kp*128 + 2c + par] = V[kc + 2kp + par][c]
#pragma unroll
    for (int it = 0; it < 8; it++) {
      int e = tid + it * 256;     // 2048 tasks: kp = e>>6, c = e&63
      int kp = e >> 6;
      int c  = e & 63;
      float v0 = Vb[(size_t)(kc + 2 * kp) * QKV_N + c];
      float v1 = Vb[(size_t)(kc + 2 * kp + 1) * QKV_N + c];
      *(float2*)&sV[kp * 128 + 2 * c] = make_float2(v0, v1);
    }
    __syncthreads();
#pragma unroll 8
    for (int kp = 0; kp < 32; kp++) {
      ull p2[4], v2[4];
#pragma unroll
      for (int r = 0; r < 4; r++)
        p2[r] = *(const ull*)&sS[(ty + 16 * r) * SS_STRIDE + kc + 2 * kp];
#pragma unroll
      for (int c = 0; c < 4; c++)
        v2[c] = *(const ull*)&sV[kp * 128 + (tx + 16 * c) * 2];
#pragma unroll
      for (int r = 0; r < 4; r++)
#pragma unroll
        for (int c = 0; c < 4; c++) ffma2(acc2[r][c], p2[r], v2[c]);
    }
  }

#pragma unroll
  for (int r = 0; r < 4; r++) {
    const float inv = 1.f / sSum[ty + 16 * r];
    float* dst = Out + ((size_t)b * SEQ + row0 + ty + 16 * r) * DM + h * HD + tx;
#pragma unroll
    for (int c = 0; c < 4; c++) {
      float lo = __uint_as_float((uint32_t)(acc2[r][c] & 0xffffffffull));
      float hi = __uint_as_float((uint32_t)(acc2[r][c] >> 32));
      dst[16 * c] = (lo + hi) * inv;
    }
  }

#else
  // ---- scalar fallback (non-sm_103a pass) ----
  float acc[4][4];
#pragma unroll
  for (int r = 0; r < 4; r++)
#pragma unroll
    for (int c = 0; c < 4; c++) acc[r][c] = 0.f;

  for (int kc = 0; kc < SEQ; kc += 64) {
    __syncthreads();
#pragma unroll
    for (int it = 0; it < 4; it++) {
      int e = tid + it * 256;
      int kk = e >> 4;
      int c = (e & 15) * 4;
      *(float4*)&sV[kk * 64 + c] = *(const float4*)(Vb + (size_t)(kc + kk) * QKV_N + c);
    }
    __syncthreads();
#pragma unroll 8
    for (int kk = 0; kk < 64; kk++) {
      float p[4], v[4];
#pragma unroll
      for (int r = 0; r < 4; r++) p[r] = sS[(ty + 16 * r) * SS_STRIDE + kc + kk];
#pragma unroll
      for (int c = 0; c < 4; c++) v[c] = sV[kk * 64 + tx + 16 * c];
#pragma unroll
      for (int r = 0; r < 4; r++)
#pragma unroll
        for (int c = 0; c < 4; c++) acc[r][c] += p[r] * v[c];
    }
  }

#pragma unroll
  for (int r = 0; r < 4; r++) {
    const float inv = 1.f / sSum[ty + 16 * r];
    float* dst = Out + ((size_t)b * SEQ + row0 + ty + 16 * r) * DM + h * HD + tx;
#pragma unroll
    for (int c = 0; c < 4; c++) dst[16 * c] = acc[r][c] * inv;
  }
#endif
}

// ---------------------------------------------------------------------------
extern "C" void kernel_launch(void* const* d_in, const int* in_sizes, int n_in,
                              void* d_out, int out_size) {
  const float* x      = (const float*)d_in[0];
  const float* prev   = (const float*)d_in[1];
  const float* Wqkv   = (const float*)d_in[2];
  const float* rrb    = (const float*)d_in[3];
  const float* rwb    = (const float*)d_in[4];
  const float* relpos = (const float*)d_in[5];
  const int*   skip   = (const int*)d_in[6];

  float* out      = (float*)d_out;                       // (8,512,1024)
  float* prev_out = out + (size_t)BATCH * SEQ * DM;      // (8,16,512,512)

  k_convA<<<(MROWS * DM / 4) / 256, 256>>>(x);
  k_convB<<<dim3(QKV_N / 32, DM / 32), 256>>>(Wqkv);

  cudaFuncSetAttribute(k_qkv_mma, cudaFuncAttributeMaxDynamicSharedMemorySize, QSMEM);
  k_qkv_mma<<<dim3(QKV_N / 128, MROWS / 128), 256, QSMEM>>>(x, Wqkv);

  cudaFuncSetAttribute(k_score, cudaFuncAttributeMaxDynamicSharedMemorySize, SC_SMEM);
  dim3 g3(SEQ / 64, SEQ / 128, BH);                      // (8, 4, 128)
  k_score<<<g3, 256, SC_SMEM>>>(rrb, rwb, relpos, prev, skip, prev_out);

  cudaFuncSetAttribute(k_av, cudaFuncAttributeMaxDynamicSharedMemorySize, SMEM_AV);
  dim3 g4(SEQ / ROWS_AV, BH);                            // (8, 128)
  k_av<<<g4, 256, SMEM_AV>>>(prev_out, out);
}

// round 13
// speedup vs baseline: 1.4974x; 1.4974x over previous
#include <cuda_runtime.h>
#include <cuda_bf16.h>
#include <cstdint>

// ---------------------------------------------------------------------------
// RelativeMultiHeadAttn (Transformer-XL style) forward.
//
// qkv = x @ Wqkv via tcgen05 bf16 split-precision GEMM (K concat trick):
//   A2 = [Xhi | Xlo | Xhi]  (4096 x 3072 bf16, K-major)
//   B2 = [Whi | Whi | Wlo]^T (3072 x 3072 bf16, K-major)
//   qkv = A2 @ B2^T  accumulated fp32 in TMEM  ==  x@W up to ~2^-18 residual.
// tcgen05 / f32x2 bodies guarded for the sm_103a arch-specific pass; the
// plain compute_103 pass compiles scalar fp32 fallbacks.
//
// score: 128x64 tiles, blocked 8x4/thread, scalar FMA + LDS.128 (the R11
// f32x2 experiment regressed: register-pair pressure). Band trick:
//   BD_shift[i,j] = (q_i + r_w) . R[:, L + j - i]
//   E_term[i,j]   = k_j . R[:, L + i - j]
// av: softmax + PV with packed f32x2 FMAs over d-pairs (layout-natural).
// ---------------------------------------------------------------------------

namespace {
constexpr int BATCH = 8;
constexpr int NH    = 16;
constexpr int SEQ   = 512;
constexpr int DM    = 1024;
constexpr int HD    = 64;
constexpr int P2    = 2 * SEQ;      // 1024
constexpr int BH    = BATCH * NH;   // 128
constexpr int QKV_N = 3 * DM;       // 3072
constexpr int MROWS = BATCH * SEQ;  // 4096
constexpr int KTOT  = 3 * DM;       // 3072 (split-K concat)
constexpr int CH    = 64;           // K chunk (one SW128 atom column of bf16)
constexpr int NCH   = KTOT / CH;    // 48
}

// scratch (static device globals: allowed; no dynamic allocation)
__device__ float         g_qkv[(size_t)MROWS * QKV_N];    // 50 MB fp32
__device__ __nv_bfloat16 g_A2[(size_t)MROWS * KTOT];      // 25 MB
__device__ __nv_bfloat16 g_B2[(size_t)QKV_N * KTOT];      // 19 MB

// Feature gate: true only in the sm_103a (arch-specific) device pass.
#ifndef __CUDA_ARCH_SPECIFIC__
#define __CUDA_ARCH_SPECIFIC__ 0
#endif
#if !defined(__CUDA_ARCH__) || defined(__CUDA_ARCH_FEAT_SM103_ALL) || \
    (__CUDA_ARCH_SPECIFIC__ == 1030)
#define HAS_TCGEN05 1
#else
#define HAS_TCGEN05 0
#endif

typedef unsigned long long ull;

// packed fp32x2 FMA: d.lo += a.lo*b.lo ; d.hi += a.hi*b.hi
#if HAS_TCGEN05
__device__ __forceinline__ void ffma2(ull& d, ull a, ull b) {
  asm("fma.rn.f32x2 %0, %1, %2, %0;" : "+l"(d) : "l"(a), "l"(b));
}
#else
__device__ __forceinline__ void ffma2(ull& d, ull a, ull b) {
  float dl = __uint_as_float((uint32_t)d),  dh = __uint_as_float((uint32_t)(d >> 32));
  float al = __uint_as_float((uint32_t)a),  ah = __uint_as_float((uint32_t)(a >> 32));
  float bl = __uint_as_float((uint32_t)b),  bh = __uint_as_float((uint32_t)(b >> 32));
  dl = fmaf(al, bl, dl);
  dh = fmaf(ah, bh, dh);
  d = (ull)__float_as_uint(dl) | ((ull)__float_as_uint(dh) << 32);
}
#endif

// ===========================================================================
// minimal sm_103a PTX helpers
// ===========================================================================
__device__ __forceinline__ uint32_t smem_u32(const void* p) {
  uint32_t a;
  asm("{ .reg .u64 t; cvta.to.shared.u64 t, %1; cvt.u32.u64 %0, t; }"
      : "=r"(a) : "l"(p));
  return a;
}
#if HAS_TCGEN05
__device__ __forceinline__ uint32_t elect_one() {
  uint32_t pred;
  asm volatile("{\n\t.reg .pred p;\n\telect.sync _|p, 0xFFFFFFFF;\n\t"
               "selp.b32 %0, 1, 0, p;\n\t}" : "=r"(pred));
  return pred;
}
__device__ __forceinline__ void mbar_init(uint32_t mbar, uint32_t cnt) {
  asm volatile("mbarrier.init.shared.b64 [%0], %1;" :: "r"(mbar), "r"(cnt) : "memory");
}
__device__ __forceinline__ void mbar_wait(uint32_t mbar, uint32_t parity) {
  asm volatile(
      "{\n\t.reg .pred P;\n\t"
      "WL_%=:\n\t"
      "mbarrier.try_wait.parity.acquire.cta.shared::cta.b64 P, [%0], %1, 0x989680;\n\t"
      "@P bra.uni WD_%=;\n\t"
      "bra.uni WL_%=;\n\t"
      "WD_%=:\n\t}"
      :: "r"(mbar), "r"(parity) : "memory");
}
__device__ __forceinline__ void tmem_alloc(uint32_t smem_dst, uint32_t ncols) {
  asm volatile("tcgen05.alloc.cta_group::1.sync.aligned.shared::cta.b32 [%0], %1;"
               :: "r"(smem_dst), "r"(ncols) : "memory");
}
__device__ __forceinline__ void tmem_relinq() {
  asm volatile("tcgen05.relinquish_alloc_permit.cta_group::1.sync.aligned;");
}
__device__ __forceinline__ void tmem_dealloc(uint32_t tmem, uint32_t ncols) {
  asm volatile("tcgen05.dealloc.cta_group::1.sync.aligned.b32 %0, %1;"
               :: "r"(tmem), "r"(ncols));
}
__device__ __forceinline__ void tcommit(uint32_t mbar) {
  asm volatile(
      "tcgen05.commit.cta_group::1.mbarrier::arrive::one.shared::cluster.b64 [%0];"
      :: "r"(mbar) : "memory");
}
__device__ __forceinline__ void fence_async_shared() {
  asm volatile("fence.proxy.async.shared::cta;" ::: "memory");
}
__device__ __forceinline__ void tfence_after() {
  asm volatile("tcgen05.fence::after_thread_sync;" ::: "memory");
}
__device__ __forceinline__ void mma_f16_ss(uint32_t d, uint64_t ad, uint64_t bd,
                                           uint32_t idesc, uint32_t en) {
  asm volatile(
      "{\n\t.reg .pred p;\n\tsetp.ne.u32 p, %5, 0;\n\t"
      "tcgen05.mma.cta_group::1.kind::f16 [%0], %1, %2, %3, {%4, %4, %4, %4}, p;\n\t}"
      :: "r"(d), "l"(ad), "l"(bd), "r"(idesc), "r"(0u), "r"(en) : "memory");
}
#define TC_LD_X32(r, addr)                                                      \
  asm volatile(                                                                 \
      "tcgen05.ld.sync.aligned.32x32b.x32.b32 "                                 \
      "{%0,%1,%2,%3,%4,%5,%6,%7,%8,%9,%10,%11,%12,%13,%14,%15,"                \
      "%16,%17,%18,%19,%20,%21,%22,%23,%24,%25,%26,%27,%28,%29,%30,%31}, [%32];" \
      : "=r"((r)[0]), "=r"((r)[1]), "=r"((r)[2]), "=r"((r)[3]),                 \
        "=r"((r)[4]), "=r"((r)[5]), "=r"((r)[6]), "=r"((r)[7]),                 \
        "=r"((r)[8]), "=r"((r)[9]), "=r"((r)[10]), "=r"((r)[11]),               \
        "=r"((r)[12]), "=r"((r)[13]), "=r"((r)[14]), "=r"((r)[15]),             \
        "=r"((r)[16]), "=r"((r)[17]), "=r"((r)[18]), "=r"((r)[19]),             \
        "=r"((r)[20]), "=r"((r)[21]), "=r"((r)[22]), "=r"((r)[23]),             \
        "=r"((r)[24]), "=r"((r)[25]), "=r"((r)[26]), "=r"((r)[27]),             \
        "=r"((r)[28]), "=r"((r)[29]), "=r"((r)[30]), "=r"((r)[31])              \
      : "r"(addr))
__device__ __forceinline__ void tc_wait_ld() {
  asm volatile("tcgen05.wait::ld.sync.aligned;" ::: "memory");
}
// SW128 K-major SMEM descriptor (LBO=1, SBO=64, version=1, layout=2)
__device__ __forceinline__ uint64_t smem_desc_sw128(uint32_t addr) {
  const uint64_t base = (uint64_t(2) << 61) | (uint64_t(1) << 46) |
                        (uint64_t(64) << 32) | (uint64_t(1) << 16);
  return base | ((uint64_t)(addr >> 4) & 0x3FFF);
}
#endif  // HAS_TCGEN05

// idesc: fp32 accum, bf16 x bf16, M=128, N=128
namespace {
constexpr uint32_t IDESC =
    (1u << 4) | (1u << 7) | (1u << 10) | ((128u / 8) << 17) | ((128u / 16) << 24);
}

// ===========================================================================
// Conversion kernels: fp32 -> split bf16 (hi/lo), B transposed to K-major
// ===========================================================================
__global__ __launch_bounds__(256) void k_convA(const float* __restrict__ X) {
  size_t i = (size_t)blockIdx.x * 256 + threadIdx.x;  // quad index
  float4 v = ((const float4*)X)[i];
  size_t m = i >> 8;
  size_t q = (i & 255) * 4;

  __nv_bfloat162 h01 = __floats2bfloat162_rn(v.x, v.y);
  __nv_bfloat162 h23 = __floats2bfloat162_rn(v.z, v.w);
  float lx = v.x - __bfloat162float(h01.x);
  float ly = v.y - __bfloat162float(h01.y);
  float lz = v.z - __bfloat162float(h23.x);
  float lw = v.w - __bfloat162float(h23.y);
  __nv_bfloat162 l01 = __floats2bfloat162_rn(lx, ly);
  __nv_bfloat162 l23 = __floats2bfloat162_rn(lz, lw);

  uint2 uh, ul;
  uh.x = *(uint32_t*)&h01; uh.y = *(uint32_t*)&h23;
  ul.x = *(uint32_t*)&l01; ul.y = *(uint32_t*)&l23;

  __nv_bfloat16* row = g_A2 + m * KTOT;
  *(uint2*)(row + q)          = uh;
  *(uint2*)(row + DM + q)     = ul;
  *(uint2*)(row + 2 * DM + q) = uh;
}

__global__ __launch_bounds__(256) void k_convB(const float* __restrict__ W) {
  __shared__ float tile[32][33];
  const int n0 = blockIdx.x * 32;
  const int k0 = blockIdx.y * 32;
  const int tid = threadIdx.x;
#pragma unroll
  for (int it = 0; it < 4; it++) {
    int e = tid + it * 256;
    int kk = e >> 5, nn = e & 31;
    tile[kk][nn] = W[(size_t)(k0 + kk) * QKV_N + n0 + nn];
  }
  __syncthreads();
#pragma unroll
  for (int it = 0; it < 4; it++) {
    int e = tid + it * 256;
    int nn = e >> 5, kk = e & 31;
    float x = tile[kk][nn];
    __nv_bfloat16 hi = __float2bfloat16_rn(x);
    __nv_bfloat16 lo = __float2bfloat16_rn(x - __bfloat162float(hi));
    __nv_bfloat16* row = g_B2 + (size_t)(n0 + nn) * KTOT;
    row[k0 + kk]          = hi;
    row[DM + k0 + kk]     = hi;
    row[2 * DM + k0 + kk] = lo;
  }
}

// ===========================================================================
// Kernel: qkv = A2 @ B2^T via tcgen05 (unchanged from round 7)
// ===========================================================================
namespace {
constexpr int QSMEM = 1024 + 4 * 16384;
}

__global__ __launch_bounds__(256) void k_qkv_mma(const float* __restrict__ X,
                                                 const float* __restrict__ W) {
#if HAS_TCGEN05
  extern __shared__ char smem[];
  const uint32_t sb = smem_u32(smem);
  const uint32_t TPTR  = sb;
  const uint32_t MBAR0 = sb + 16;
  const uint32_t MBAR1 = sb + 24;
  const uint32_t STAGE = sb + 1024;

  const int tid = threadIdx.x;
  const int wid = tid >> 5;

  if (wid == 0) tmem_alloc(TPTR, 128);
  if (tid == 0) { mbar_init(MBAR0, 1); mbar_init(MBAR1, 1); }
  __syncthreads();
  uint32_t tmem;
  asm volatile("ld.shared.b32 %0, [%1];" : "=r"(tmem) : "r"(TPTR));
  if (wid == 0) tmem_relinq();

  const int m0 = blockIdx.y * 128;
  const int n0 = blockIdx.x * 128;
  const __nv_bfloat16* Ag = g_A2 + (size_t)m0 * KTOT;
  const __nv_bfloat16* Bg = g_B2 + (size_t)n0 * KTOT;

  const int row = tid >> 1;
  const int sg0 = (tid & 1) * 4;

  uint32_t ph0 = 0, ph1 = 0;
  for (int t = 0; t < NCH; t++) {
    const int p = t & 1;
    const uint32_t Abase = STAGE + p * 32768;
    const uint32_t Bbase = Abase + 16384;
    if (t >= 2) {
      if (p == 0) { mbar_wait(MBAR0, ph0); ph0 ^= 1; }
      else        { mbar_wait(MBAR1, ph1); ph1 ^= 1; }
    }
    const int kc = t * CH;
    uint4 av[4], bv[4];
    const char* arow = (const char*)(Ag + (size_t)row * KTOT + kc);
    const char* brow = (const char*)(Bg + (size_t)row * KTOT + kc);
#pragma unroll
    for (int s = 0; s < 4; s++) {
      av[s] = *(const uint4*)(arow + (sg0 + s) * 16);
      bv[s] = *(const uint4*)(brow + (sg0 + s) * 16);
    }
#pragma unroll
    for (int s = 0; s < 4; s++) {
      uint32_t off = row * 128 + (sg0 + s) * 16;
      uint32_t sw = off ^ ((off >> 3) & 0x70);
      *(uint4*)(smem + (Abase - sb) + sw) = av[s];
      *(uint4*)(smem + (Bbase - sb) + sw) = bv[s];
    }
    __syncthreads();
    if (wid == 0) {
      if (elect_one()) {
        fence_async_shared();
        uint64_t ad = smem_desc_sw128(Abase);
        uint64_t bd = smem_desc_sw128(Bbase);
#pragma unroll
        for (int k = 0; k < 4; k++)
          mma_f16_ss(tmem, ad + k * 2, bd + k * 2, IDESC, (t > 0 || k > 0) ? 1u : 0u);
        tcommit(p == 0 ? MBAR0 : MBAR1);
      }
    }
  }
  mbar_wait(MBAR1, ph1);
  tfence_after();

  if (wid < 4) {
    const int lid = tid & 31;
    const int orow = m0 + wid * 32 + lid;
#pragma unroll
    for (int cb = 0; cb < 128; cb += 32) {
      uint32_t d[32];
      TC_LD_X32(d, tmem + cb);
      tc_wait_ld();
      float* dst = g_qkv + (size_t)orow * QKV_N + n0 + cb;
#pragma unroll
      for (int c = 0; c < 32; c += 4)
        *(float4*)(dst + c) = make_float4(__uint_as_float(d[c]),
                                          __uint_as_float(d[c + 1]),
                                          __uint_as_float(d[c + 2]),
                                          __uint_as_float(d[c + 3]));
    }
  }
  __syncthreads();
  if (wid == 0) tmem_dealloc(tmem, 128);

#else  // ------------- FFMA fallback (non-sm_103a pass; still correct) -------
  extern __shared__ char smemraw[];
  float* sA = (float*)smemraw;
  float* sB = sA + 16 * 128;
  const int K = DM, N = QKV_N;
  const int tid = threadIdx.x;
  const int tx = tid & 15, ty = tid >> 4;
  const int row0 = blockIdx.y * 128;
  const int col0 = blockIdx.x * 128;

  float acc[8][8];
#pragma unroll
  for (int r = 0; r < 8; r++)
#pragma unroll
    for (int c = 0; c < 8; c++) acc[r][c] = 0.f;

  for (int kk = 0; kk < K; kk += 16) {
#pragma unroll
    for (int it = 0; it < 2; it++) {
      int e = tid + it * 256;
      int ar = e >> 2;
      int ac = (e & 3) * 4;
      float4 a4 = *(const float4*)(X + (size_t)(row0 + ar) * K + kk + ac);
      sA[(ac + 0) * 128 + ar] = a4.x;
      sA[(ac + 1) * 128 + ar] = a4.y;
      sA[(ac + 2) * 128 + ar] = a4.z;
      sA[(ac + 3) * 128 + ar] = a4.w;
    }
#pragma unroll
    for (int it = 0; it < 2; it++) {
      int e = tid + it * 256;
      int br = e >> 5;
      int bc = (e & 31) * 4;
      *(float4*)&sB[br * 128 + bc] = *(const float4*)(W + (size_t)(kk + br) * N + col0 + bc);
    }
    __syncthreads();
#pragma unroll
    for (int k = 0; k < 16; k++) {
      float ar[8], bc[8];
      *(float4*)&ar[0] = *(float4*)&sA[k * 128 + ty * 8];
      *(float4*)&ar[4] = *(float4*)&sA[k * 128 + ty * 8 + 4];
      *(float4*)&bc[0] = *(float4*)&sB[k * 128 + tx * 8];
      *(float4*)&bc[4] = *(float4*)&sB[k * 128 + tx * 8 + 4];
#pragma unroll
      for (int r = 0; r < 8; r++)
#pragma unroll
        for (int c = 0; c < 8; c++) acc[r][c] += ar[r] * bc[c];
    }
    __syncthreads();
  }
#pragma unroll
  for (int r = 0; r < 8; r++) {
    float* dst = g_qkv + (size_t)(row0 + ty * 8 + r) * QKV_N + col0 + tx * 8;
    *(float4*)dst       = make_float4(acc[r][0], acc[r][1], acc[r][2], acc[r][3]);
    *(float4*)(dst + 4) = make_float4(acc[r][4], acc[r][5], acc[r][6], acc[r][7]);
  }
#endif
}

// ===========================================================================
// Kernel: fused score. 128x64 tile, 256 threads, blocked 8x4 per thread,
// scalar FMA with LDS.128 operands (144B LDS per 32 outputs per d).
// Bands are 191 wide (row span 128), d-chunked (DCH=16).
// attn_score = (AC + BD + E)/8 + prev -> prev_out
// ===========================================================================
namespace {
constexpr int DCH     = 16;
constexpr int BSTR    = 192;   // band row stride (191 used)
constexpr int SC_SMEM = (64 * 128 + 64 * 64 + 2 * DCH * BSTR) * 4;  // 73728 B
}

__global__ __launch_bounds__(256) void k_score(const float* __restrict__ rrb,
                                               const float* __restrict__ rwb,
                                               const float* __restrict__ relpos,
                                               const float* __restrict__ prev,
                                               const int* __restrict__ skip,
                                               float* __restrict__ prev_out) {
  extern __shared__ float smemf[];
  float* sQT = smemf;               // [64 d][128 r]
  float* sKT = sQT + 64 * 128;      // [64 d][64 c]
  float* sRq = sKT + 64 * 64;       // [DCH][BSTR] band chunk for BD (191 used)
  float* sRe = sRq + DCH * BSTR;    // [DCH][BSTR] band chunk for E
  __shared__ float cK[64];          // rrb . k_j
  __shared__ float cRq[BSTR];       // rwb . R_t (191 used), accumulated

  const int bh = blockIdx.z;
  const int b = bh >> 4, h = bh & 15;
  const int tid = threadIdx.x;
  const int tx = tid & 15, ty = tid >> 4;
  const int i0 = blockIdx.y * 128;
  const int j0 = blockIdx.x * 64;

  const float* Qb = g_qkv + (size_t)(b * SEQ) * QKV_N + h * HD;
  const float* Kb = Qb + DM;

  // load Q tile (128 rows) transposed into smem (d-major)
#pragma unroll
  for (int it = 0; it < 8; it++) {
    int e = tid + it * 256;       // 128 rows x 16 float4
    int r = e & 127;
    int c = (e >> 7) * 4;
    float4 q4 = *(const float4*)(Qb + (size_t)(i0 + r) * QKV_N + c);
    sQT[(c + 0) * 128 + r] = q4.x;
    sQT[(c + 1) * 128 + r] = q4.y;
    sQT[(c + 2) * 128 + r] = q4.z;
    sQT[(c + 3) * 128 + r] = q4.w;
  }
  // load K tile (64 cols) transposed
#pragma unroll
  for (int it = 0; it < 4; it++) {
    int e = tid + it * 256;       // 64 rows x 16 float4
    int r = e & 63;
    int c = (e >> 6) * 4;
    float4 k4 = *(const float4*)(Kb + (size_t)(j0 + r) * QKV_N + c);
    sKT[(c + 0) * 64 + r] = k4.x;
    sKT[(c + 1) * 64 + r] = k4.y;
    sKT[(c + 2) * 64 + r] = k4.z;
    sKT[(c + 3) * 64 + r] = k4.w;
  }
  if (tid < BSTR) cRq[tid] = 0.f;
  __syncthreads();

  // rank-1 correction cK (needs full-K sKT)
  if (tid < 64) {
    float s = 0.f;
#pragma unroll
    for (int d = 0; d < 64; d++) s += rrb[h * HD + d] * sKT[d * 64 + tid];
    cK[tid] = s;
  }

  float acc[8][4];
#pragma unroll
  for (int r = 0; r < 8; r++)
#pragma unroll
    for (int c = 0; c < 4; c++) acc[r][c] = 0.f;

  // blocked tile: rows i0 + ty*8 + r (r<8), cols j0 + tx*4 + c (c<4)
  // BD band x = (j_local - i_local) + 127; thread base xq0 = tx*4 - ty*8 + 120
  //   (x for (r,c) = xq0 + 7 + c - r; reads xq0..xq0+10, 16B-aligned base)
  // E  band x = (i_local - j_local) + 63; thread base xe0 = ty*8 - tx*4 + 60
  //   (x for (r,c) = xe0 + 3 + r - c; reads xe0..xe0+10)
  const int xq0 = tx * 4 - ty * 8 + 120;   // in [0, 180]
  const int xe0 = ty * 8 - tx * 4 + 60;    // in [0, 180]
  const int q0g = SEQ + (j0 - i0) - 127;   // global band starts, within [1,1023]
  const int u0g = SEQ + (i0 - j0) - 63;

  for (int chk = 0; chk < 64 / DCH; chk++) {
    const int d0 = chk * DCH;
    // fill band chunks (191 of BSTR used)
    for (int e = tid; e < DCH * BSTR; e += 256) {
      int dl = e / BSTR, x = e - dl * BSTR;
      if (x < 191) {
        sRq[dl * BSTR + x] = relpos[(size_t)(d0 + dl) * P2 + q0g + x];
        sRe[dl * BSTR + x] = relpos[(size_t)(d0 + dl) * P2 + u0g + x];
      }
    }
    __syncthreads();

    // accumulate cRq partial for this chunk
    if (tid < 191) {
      float s = 0.f;
#pragma unroll
      for (int dl = 0; dl < DCH; dl++)
        s += rwb[h * HD + d0 + dl] * sRq[dl * BSTR + tid];
      cRq[tid] += s;
    }

#pragma unroll
    for (int dl = 0; dl < DCH; dl++) {
      const int d = d0 + dl;
      float a[8], bb[4], rq[12], re[12];
      *(float4*)&a[0]  = *(float4*)&sQT[d * 128 + ty * 8];
      *(float4*)&a[4]  = *(float4*)&sQT[d * 128 + ty * 8 + 4];
      *(float4*)&bb[0] = *(float4*)&sKT[d * 64 + tx * 4];
      *(float4*)&rq[0] = *(float4*)&sRq[dl * BSTR + xq0];
      *(float4*)&rq[4] = *(float4*)&sRq[dl * BSTR + xq0 + 4];
      *(float4*)&rq[8] = *(float4*)&sRq[dl * BSTR + xq0 + 8];
      *(float4*)&re[0] = *(float4*)&sRe[dl * BSTR + xe0];
      *(float4*)&re[4] = *(float4*)&sRe[dl * BSTR + xe0 + 4];
      *(float4*)&re[8] = *(float4*)&sRe[dl * BSTR + xe0 + 8];
#pragma unroll
      for (int r = 0; r < 8; r++)
#pragma unroll
        for (int c = 0; c < 4; c++)
          acc[r][c] += a[r] * bb[c] + a[r] * rq[c - r + 7] + bb[c] * re[r - c + 3];
    }
    __syncthreads();
  }

  const int sk = *skip;
  const float* prevb = prev + (size_t)bh * SEQ * SEQ;
  float* outb = prev_out + (size_t)bh * SEQ * SEQ;

#pragma unroll
  for (int r = 0; r < 8; r++) {
    const int i = i0 + ty * 8 + r;
    const int j = j0 + tx * 4;
    float4 p = make_float4(0.f, 0.f, 0.f, 0.f);
    if (sk) p = *(const float4*)(prevb + (size_t)i * SEQ + j);
    float4 o;
    o.x = (acc[r][0] + cK[tx * 4 + 0] + cRq[xq0 + 7 + 0 - r]) * 0.125f + p.x;
    o.y = (acc[r][1] + cK[tx * 4 + 1] + cRq[xq0 + 7 + 1 - r]) * 0.125f + p.y;
    o.z = (acc[r][2] + cK[tx * 4 + 2] + cRq[xq0 + 7 + 2 - r]) * 0.125f + p.z;
    o.w = (acc[r][3] + cK[tx * 4 + 3] + cRq[xq0 + 7 + 3 - r]) * 0.125f + p.w;
    *(float4*)(outb + (size_t)i * SEQ + j) = o;
  }
}

// ===========================================================================
// Kernel: out = softmax(S) @ V. 64 rows/block, 4x4 tile.
// sm_103a path: packed f32x2 FMAs over d-pairs, V stored d-interleaved.
// (unchanged from round 10)
// ===========================================================================
namespace {
constexpr int ROWS_AV   = 64;
constexpr int SS_STRIDE = 516;
constexpr int SMEM_AV   = (ROWS_AV * SS_STRIDE + 64 * 64) * 4;  // 148480 B
}

__global__ __launch_bounds__(256) void k_av(const float* __restrict__ Sglob,
                                            float* __restrict__ Out) {
  extern __shared__ float smemf[];
  float* sS = smemf;
  float* sV = smemf + ROWS_AV * SS_STRIDE;   // f32x2 path: [32 kp][64 c][2]
  __shared__ float sSum[ROWS_AV];

  const int bh = blockIdx.y;
  const int b = bh >> 4, h = bh & 15;
  const int row0 = blockIdx.x * ROWS_AV;
  const int tid = threadIdx.x;
  const int tx = tid & 15, ty = tid >> 4;
  const float* Sb = Sglob + ((size_t)bh * SEQ + row0) * SEQ;

#pragma unroll
  for (int it = 0; it < 32; it++) {
    int e = tid + it * 256;
    int r = e >> 7;
    int c = (e & 127) * 4;
    *(float4*)&sS[r * SS_STRIDE + c] = *(const float4*)(Sb + (size_t)r * SEQ + c);
  }
  __syncthreads();

  {
    const int warp = tid >> 5, lane = tid & 31;
#pragma unroll
    for (int rr = 0; rr < 8; rr++) {
      int row = warp * 8 + rr;
      float* srow = sS + row * SS_STRIDE;
      float mx = -1e30f;
      for (int c = lane; c < SEQ; c += 32) mx = fmaxf(mx, srow[c]);
#pragma unroll
      for (int o = 16; o > 0; o >>= 1) mx = fmaxf(mx, __shfl_xor_sync(0xffffffffu, mx, o));
      float sum = 0.f;
      for (int c = lane; c < SEQ; c += 32) {
        float p = __expf(srow[c] - mx);
        srow[c] = p;
        sum += p;
      }
#pragma unroll
      for (int o = 16; o > 0; o >>= 1) sum += __shfl_xor_sync(0xffffffffu, sum, o);
      if (lane == 0) sSum[row] = sum;
    }
  }

  const float* Vb = g_qkv + (size_t)(b * SEQ) * QKV_N + 2 * DM + h * HD;

#if HAS_TCGEN05
  // ---- packed f32x2 PV: accumulate even-d in lane0, odd-d in lane1 ----
  ull acc2[4][4];
#pragma unroll
  for (int r = 0; r < 4; r++)
#pragma unroll
    for (int c = 0; c < 4; c++) acc2[r][c] = 0ull;

  for (int kc = 0; kc < SEQ; kc += 64) {
    __syncthreads();
    // fill V interleaved: sV[kp*128 + 2c + par] = V[kc + 2kp + par][c]
#pragma unroll
    for (int it = 0; it < 8; it++) {
      int e = tid + it * 256;     // 2048 tasks: kp = e>>6, c = e&63
      int kp = e >> 6;
      int c  = e & 63;
      float v0 = Vb[(size_t)(kc + 2 * kp) * QKV_N + c];
      float v1 = Vb[(size_t)(kc + 2 * kp + 1) * QKV_N + c];
      *(float2*)&sV[kp * 128 + 2 * c] = make_float2(v0, v1);
    }
    __syncthreads();
#pragma unroll 8
    for (int kp = 0; kp < 32; kp++) {
      ull p2[4], v2[4];
#pragma unroll
      for (int r = 0; r < 4; r++)
        p2[r] = *(const ull*)&sS[(ty + 16 * r) * SS_STRIDE + kc + 2 * kp];
#pragma unroll
      for (int c = 0; c < 4; c++)
        v2[c] = *(const ull*)&sV[kp * 128 + (tx + 16 * c) * 2];
#pragma unroll
      for (int r = 0; r < 4; r++)
#pragma unroll
        for (int c = 0; c < 4; c++) ffma2(acc2[r][c], p2[r], v2[c]);
    }
  }

#pragma unroll
  for (int r = 0; r < 4; r++) {
    const float inv = 1.f / sSum[ty + 16 * r];
    float* dst = Out + ((size_t)b * SEQ + row0 + ty + 16 * r) * DM + h * HD + tx;
#pragma unroll
    for (int c = 0; c < 4; c++) {
      float lo = __uint_as_float((uint32_t)(acc2[r][c] & 0xffffffffull));
      float hi = __uint_as_float((uint32_t)(acc2[r][c] >> 32));
      dst[16 * c] = (lo + hi) * inv;
    }
  }

#else
  // ---- scalar fallback (non-sm_103a pass) ----
  float acc[4][4];
#pragma unroll
  for (int r = 0; r < 4; r++)
#pragma unroll
    for (int c = 0; c < 4; c++) acc[r][c] = 0.f;

  for (int kc = 0; kc < SEQ; kc += 64) {
    __syncthreads();
#pragma unroll
    for (int it = 0; it < 4; it++) {
      int e = tid + it * 256;
      int kk = e >> 4;
      int c = (e & 15) * 4;
      *(float4*)&sV[kk * 64 + c] = *(const float4*)(Vb + (size_t)(kc + kk) * QKV_N + c);
    }
    __syncthreads();
#pragma unroll 8
    for (int kk = 0; kk < 64; kk++) {
      float p[4], v[4];
#pragma unroll
      for (int r = 0; r < 4; r++) p[r] = sS[(ty + 16 * r) * SS_STRIDE + kc + kk];
#pragma unroll
      for (int c = 0; c < 4; c++) v[c] = sV[kk * 64 + tx + 16 * c];
#pragma unroll
      for (int r = 0; r < 4; r++)
#pragma unroll
        for (int c = 0; c < 4; c++) acc[r][c] += p[r] * v[c];
    }
  }

#pragma unroll
  for (int r = 0; r < 4; r++) {
    const float inv = 1.f / sSum[ty + 16 * r];
    float* dst = Out + ((size_t)b * SEQ + row0 + ty + 16 * r) * DM + h * HD + tx;
#pragma unroll
    for (int c = 0; c < 4; c++) dst[16 * c] = acc[r][c] * inv;
  }
#endif
}

// ---------------------------------------------------------------------------
extern "C" void kernel_launch(void* const* d_in, const int* in_sizes, int n_in,
                              void* d_out, int out_size) {
  const float* x      = (const float*)d_in[0];
  const float* prev   = (const float*)d_in[1];
  const float* Wqkv   = (const float*)d_in[2];
  const float* rrb    = (const float*)d_in[3];
  const float* rwb    = (const float*)d_in[4];
  const float* relpos = (const float*)d_in[5];
  const int*   skip   = (const int*)d_in[6];

  float* out      = (float*)d_out;                       // (8,512,1024)
  float* prev_out = out + (size_t)BATCH * SEQ * DM;      // (8,16,512,512)

  k_convA<<<(MROWS * DM / 4) / 256, 256>>>(x);
  k_convB<<<dim3(QKV_N / 32, DM / 32), 256>>>(Wqkv);

  cudaFuncSetAttribute(k_qkv_mma, cudaFuncAttributeMaxDynamicSharedMemorySize, QSMEM);
  k_qkv_mma<<<dim3(QKV_N / 128, MROWS / 128), 256, QSMEM>>>(x, Wqkv);

  cudaFuncSetAttribute(k_score, cudaFuncAttributeMaxDynamicSharedMemorySize, SC_SMEM);
  dim3 g3(SEQ / 64, SEQ / 128, BH);                      // (8, 4, 128)
  k_score<<<g3, 256, SC_SMEM>>>(rrb, rwb, relpos, prev, skip, prev_out);

  cudaFuncSetAttribute(k_av, cudaFuncAttributeMaxDynamicSharedMemorySize, SMEM_AV);
  dim3 g4(SEQ / ROWS_AV, BH);                            // (8, 128)
  k_av<<<g4, 256, SMEM_AV>>>(prev_out, out);
}

// round 14
// speedup vs baseline: 1.5921x; 1.0632x over previous
#include <cuda_runtime.h>
#include <cuda_bf16.h>
#include <cstdint>

// ---------------------------------------------------------------------------
// RelativeMultiHeadAttn (Transformer-XL style) forward.
//
// qkv = x @ Wqkv via tcgen05 bf16 split-precision GEMM (K concat trick):
//   A2 = [Xhi | Xlo | Xhi]  (4096 x 3072 bf16, K-major)
//   B2 = [Whi | Whi | Wlo]^T (3072 x 3072 bf16, K-major)
//   qkv = A2 @ B2^T  accumulated fp32 in TMEM  ==  x@W up to ~2^-18 residual.
// tcgen05 / f32x2 bodies guarded for the sm_103a arch-specific pass; the
// plain compute_103 pass compiles scalar fp32 fallbacks.
//
// score: 128x64 tiles, blocked 8x4/thread, scalar FMA + LDS.128 (measured at
// 76% of the scalar-FFMA floor; frozen). Band trick:
//   BD_shift[i,j] = (q_i + r_w) . R[:, L + j - i]
//   E_term[i,j]   = k_j . R[:, L + i - j]
// av: fused load+exp+sum softmax (no max: scores bounded ~12, exp far from
// overflow) + PV with packed f32x2 FMAs over d-pairs.
// ---------------------------------------------------------------------------

namespace {
constexpr int BATCH = 8;
constexpr int NH    = 16;
constexpr int SEQ   = 512;
constexpr int DM    = 1024;
constexpr int HD    = 64;
constexpr int P2    = 2 * SEQ;      // 1024
constexpr int BH    = BATCH * NH;   // 128
constexpr int QKV_N = 3 * DM;       // 3072
constexpr int MROWS = BATCH * SEQ;  // 4096
constexpr int KTOT  = 3 * DM;       // 3072 (split-K concat)
constexpr int CH    = 64;           // K chunk (one SW128 atom column of bf16)
constexpr int NCH   = KTOT / CH;    // 48
}

// scratch (static device globals: allowed; no dynamic allocation)
__device__ float         g_qkv[(size_t)MROWS * QKV_N];    // 50 MB fp32
__device__ __nv_bfloat16 g_A2[(size_t)MROWS * KTOT];      // 25 MB
__device__ __nv_bfloat16 g_B2[(size_t)QKV_N * KTOT];      // 19 MB

// Feature gate: true only in the sm_103a (arch-specific) device pass.
#ifndef __CUDA_ARCH_SPECIFIC__
#define __CUDA_ARCH_SPECIFIC__ 0
#endif
#if !defined(__CUDA_ARCH__) || defined(__CUDA_ARCH_FEAT_SM103_ALL) || \
    (__CUDA_ARCH_SPECIFIC__ == 1030)
#define HAS_TCGEN05 1
#else
#define HAS_TCGEN05 0
#endif

typedef unsigned long long ull;

// packed fp32x2 FMA: d.lo += a.lo*b.lo ; d.hi += a.hi*b.hi
#if HAS_TCGEN05
__device__ __forceinline__ void ffma2(ull& d, ull a, ull b) {
  asm("fma.rn.f32x2 %0, %1, %2, %0;" : "+l"(d) : "l"(a), "l"(b));
}
#else
__device__ __forceinline__ void ffma2(ull& d, ull a, ull b) {
  float dl = __uint_as_float((uint32_t)d),  dh = __uint_as_float((uint32_t)(d >> 32));
  float al = __uint_as_float((uint32_t)a),  ah = __uint_as_float((uint32_t)(a >> 32));
  float bl = __uint_as_float((uint32_t)b),  bh = __uint_as_float((uint32_t)(b >> 32));
  dl = fmaf(al, bl, dl);
  dh = fmaf(ah, bh, dh);
  d = (ull)__float_as_uint(dl) | ((ull)__float_as_uint(dh) << 32);
}
#endif

// ===========================================================================
// minimal sm_103a PTX helpers
// ===========================================================================
__device__ __forceinline__ uint32_t smem_u32(const void* p) {
  uint32_t a;
  asm("{ .reg .u64 t; cvta.to.shared.u64 t, %1; cvt.u32.u64 %0, t; }"
      : "=r"(a) : "l"(p));
  return a;
}
#if HAS_TCGEN05
__device__ __forceinline__ uint32_t elect_one() {
  uint32_t pred;
  asm volatile("{\n\t.reg .pred p;\n\telect.sync _|p, 0xFFFFFFFF;\n\t"
               "selp.b32 %0, 1, 0, p;\n\t}" : "=r"(pred));
  return pred;
}
__device__ __forceinline__ void mbar_init(uint32_t mbar, uint32_t cnt) {
  asm volatile("mbarrier.init.shared.b64 [%0], %1;" :: "r"(mbar), "r"(cnt) : "memory");
}
__device__ __forceinline__ void mbar_wait(uint32_t mbar, uint32_t parity) {
  asm volatile(
      "{\n\t.reg .pred P;\n\t"
      "WL_%=:\n\t"
      "mbarrier.try_wait.parity.acquire.cta.shared::cta.b64 P, [%0], %1, 0x989680;\n\t"
      "@P bra.uni WD_%=;\n\t"
      "bra.uni WL_%=;\n\t"
      "WD_%=:\n\t}"
      :: "r"(mbar), "r"(parity) : "memory");
}
__device__ __forceinline__ void tmem_alloc(uint32_t smem_dst, uint32_t ncols) {
  asm volatile("tcgen05.alloc.cta_group::1.sync.aligned.shared::cta.b32 [%0], %1;"
               :: "r"(smem_dst), "r"(ncols) : "memory");
}
__device__ __forceinline__ void tmem_relinq() {
  asm volatile("tcgen05.relinquish_alloc_permit.cta_group::1.sync.aligned;");
}
__device__ __forceinline__ void tmem_dealloc(uint32_t tmem, uint32_t ncols) {
  asm volatile("tcgen05.dealloc.cta_group::1.sync.aligned.b32 %0, %1;"
               :: "r"(tmem), "r"(ncols));
}
__device__ __forceinline__ void tcommit(uint32_t mbar) {
  asm volatile(
      "tcgen05.commit.cta_group::1.mbarrier::arrive::one.shared::cluster.b64 [%0];"
      :: "r"(mbar) : "memory");
}
__device__ __forceinline__ void fence_async_shared() {
  asm volatile("fence.proxy.async.shared::cta;" ::: "memory");
}
__device__ __forceinline__ void tfence_after() {
  asm volatile("tcgen05.fence::after_thread_sync;" ::: "memory");
}
__device__ __forceinline__ void mma_f16_ss(uint32_t d, uint64_t ad, uint64_t bd,
                                           uint32_t idesc, uint32_t en) {
  asm volatile(
      "{\n\t.reg .pred p;\n\tsetp.ne.u32 p, %5, 0;\n\t"
      "tcgen05.mma.cta_group::1.kind::f16 [%0], %1, %2, %3, {%4, %4, %4, %4}, p;\n\t}"
      :: "r"(d), "l"(ad), "l"(bd), "r"(idesc), "r"(0u), "r"(en) : "memory");
}
#define TC_LD_X32(r, addr)                                                      \
  asm volatile(                                                                 \
      "tcgen05.ld.sync.aligned.32x32b.x32.b32 "                                 \
      "{%0,%1,%2,%3,%4,%5,%6,%7,%8,%9,%10,%11,%12,%13,%14,%15,"                \
      "%16,%17,%18,%19,%20,%21,%22,%23,%24,%25,%26,%27,%28,%29,%30,%31}, [%32];" \
      : "=r"((r)[0]), "=r"((r)[1]), "=r"((r)[2]), "=r"((r)[3]),                 \
        "=r"((r)[4]), "=r"((r)[5]), "=r"((r)[6]), "=r"((r)[7]),                 \
        "=r"((r)[8]), "=r"((r)[9]), "=r"((r)[10]), "=r"((r)[11]),               \
        "=r"((r)[12]), "=r"((r)[13]), "=r"((r)[14]), "=r"((r)[15]),             \
        "=r"((r)[16]), "=r"((r)[17]), "=r"((r)[18]), "=r"((r)[19]),             \
        "=r"((r)[20]), "=r"((r)[21]), "=r"((r)[22]), "=r"((r)[23]),             \
        "=r"((r)[24]), "=r"((r)[25]), "=r"((r)[26]), "=r"((r)[27]),             \
        "=r"((r)[28]), "=r"((r)[29]), "=r"((r)[30]), "=r"((r)[31])              \
      : "r"(addr))
__device__ __forceinline__ void tc_wait_ld() {
  asm volatile("tcgen05.wait::ld.sync.aligned;" ::: "memory");
}
// SW128 K-major SMEM descriptor (LBO=1, SBO=64, version=1, layout=2)
__device__ __forceinline__ uint64_t smem_desc_sw128(uint32_t addr) {
  const uint64_t base = (uint64_t(2) << 61) | (uint64_t(1) << 46) |
                        (uint64_t(64) << 32) | (uint64_t(1) << 16);
  return base | ((uint64_t)(addr >> 4) & 0x3FFF);
}
#endif  // HAS_TCGEN05

// idesc: fp32 accum, bf16 x bf16, M=128, N=128
namespace {
constexpr uint32_t IDESC =
    (1u << 4) | (1u << 7) | (1u << 10) | ((128u / 8) << 17) | ((128u / 16) << 24);
}

// ===========================================================================
// Conversion kernels: fp32 -> split bf16 (hi/lo), B transposed to K-major
// ===========================================================================
__global__ __launch_bounds__(256) void k_convA(const float* __restrict__ X) {
  size_t i = (size_t)blockIdx.x * 256 + threadIdx.x;  // quad index
  float4 v = ((const float4*)X)[i];
  size_t m = i >> 8;
  size_t q = (i & 255) * 4;

  __nv_bfloat162 h01 = __floats2bfloat162_rn(v.x, v.y);
  __nv_bfloat162 h23 = __floats2bfloat162_rn(v.z, v.w);
  float lx = v.x - __bfloat162float(h01.x);
  float ly = v.y - __bfloat162float(h01.y);
  float lz = v.z - __bfloat162float(h23.x);
  float lw = v.w - __bfloat162float(h23.y);
  __nv_bfloat162 l01 = __floats2bfloat162_rn(lx, ly);
  __nv_bfloat162 l23 = __floats2bfloat162_rn(lz, lw);

  uint2 uh, ul;
  uh.x = *(uint32_t*)&h01; uh.y = *(uint32_t*)&h23;
  ul.x = *(uint32_t*)&l01; ul.y = *(uint32_t*)&l23;

  __nv_bfloat16* row = g_A2 + m * KTOT;
  *(uint2*)(row + q)          = uh;
  *(uint2*)(row + DM + q)     = ul;
  *(uint2*)(row + 2 * DM + q) = uh;
}

__global__ __launch_bounds__(256) void k_convB(const float* __restrict__ W) {
  __shared__ float tile[32][33];
  const int n0 = blockIdx.x * 32;
  const int k0 = blockIdx.y * 32;
  const int tid = threadIdx.x;
#pragma unroll
  for (int it = 0; it < 4; it++) {
    int e = tid + it * 256;
    int kk = e >> 5, nn = e & 31;
    tile[kk][nn] = W[(size_t)(k0 + kk) * QKV_N + n0 + nn];
  }
  __syncthreads();
#pragma unroll
  for (int it = 0; it < 4; it++) {
    int e = tid + it * 256;
    int nn = e >> 5, kk = e & 31;
    float x = tile[kk][nn];
    __nv_bfloat16 hi = __float2bfloat16_rn(x);
    __nv_bfloat16 lo = __float2bfloat16_rn(x - __bfloat162float(hi));
    __nv_bfloat16* row = g_B2 + (size_t)(n0 + nn) * KTOT;
    row[k0 + kk]          = hi;
    row[DM + k0 + kk]     = hi;
    row[2 * DM + k0 + kk] = lo;
  }
}

// ===========================================================================
// Kernel: qkv = A2 @ B2^T via tcgen05 (unchanged from round 7)
// ===========================================================================
namespace {
constexpr int QSMEM = 1024 + 4 * 16384;
}

__global__ __launch_bounds__(256) void k_qkv_mma(const float* __restrict__ X,
                                                 const float* __restrict__ W) {
#if HAS_TCGEN05
  extern __shared__ char smem[];
  const uint32_t sb = smem_u32(smem);
  const uint32_t TPTR  = sb;
  const uint32_t MBAR0 = sb + 16;
  const uint32_t MBAR1 = sb + 24;
  const uint32_t STAGE = sb + 1024;

  const int tid = threadIdx.x;
  const int wid = tid >> 5;

  if (wid == 0) tmem_alloc(TPTR, 128);
  if (tid == 0) { mbar_init(MBAR0, 1); mbar_init(MBAR1, 1); }
  __syncthreads();
  uint32_t tmem;
  asm volatile("ld.shared.b32 %0, [%1];" : "=r"(tmem) : "r"(TPTR));
  if (wid == 0) tmem_relinq();

  const int m0 = blockIdx.y * 128;
  const int n0 = blockIdx.x * 128;
  const __nv_bfloat16* Ag = g_A2 + (size_t)m0 * KTOT;
  const __nv_bfloat16* Bg = g_B2 + (size_t)n0 * KTOT;

  const int row = tid >> 1;
  const int sg0 = (tid & 1) * 4;

  uint32_t ph0 = 0, ph1 = 0;
  for (int t = 0; t < NCH; t++) {
    const int p = t & 1;
    const uint32_t Abase = STAGE + p * 32768;
    const uint32_t Bbase = Abase + 16384;
    if (t >= 2) {
      if (p == 0) { mbar_wait(MBAR0, ph0); ph0 ^= 1; }
      else        { mbar_wait(MBAR1, ph1); ph1 ^= 1; }
    }
    const int kc = t * CH;
    uint4 av[4], bv[4];
    const char* arow = (const char*)(Ag + (size_t)row * KTOT + kc);
    const char* brow = (const char*)(Bg + (size_t)row * KTOT + kc);
#pragma unroll
    for (int s = 0; s < 4; s++) {
      av[s] = *(const uint4*)(arow + (sg0 + s) * 16);
      bv[s] = *(const uint4*)(brow + (sg0 + s) * 16);
    }
#pragma unroll
    for (int s = 0; s < 4; s++) {
      uint32_t off = row * 128 + (sg0 + s) * 16;
      uint32_t sw = off ^ ((off >> 3) & 0x70);
      *(uint4*)(smem + (Abase - sb) + sw) = av[s];
      *(uint4*)(smem + (Bbase - sb) + sw) = bv[s];
    }
    __syncthreads();
    if (wid == 0) {
      if (elect_one()) {
        fence_async_shared();
        uint64_t ad = smem_desc_sw128(Abase);
        uint64_t bd = smem_desc_sw128(Bbase);
#pragma unroll
        for (int k = 0; k < 4; k++)
          mma_f16_ss(tmem, ad + k * 2, bd + k * 2, IDESC, (t > 0 || k > 0) ? 1u : 0u);
        tcommit(p == 0 ? MBAR0 : MBAR1);
      }
    }
  }
  mbar_wait(MBAR1, ph1);
  tfence_after();

  if (wid < 4) {
    const int lid = tid & 31;
    const int orow = m0 + wid * 32 + lid;
#pragma unroll
    for (int cb = 0; cb < 128; cb += 32) {
      uint32_t d[32];
      TC_LD_X32(d, tmem + cb);
      tc_wait_ld();
      float* dst = g_qkv + (size_t)orow * QKV_N + n0 + cb;
#pragma unroll
      for (int c = 0; c < 32; c += 4)
        *(float4*)(dst + c) = make_float4(__uint_as_float(d[c]),
                                          __uint_as_float(d[c + 1]),
                                          __uint_as_float(d[c + 2]),
                                          __uint_as_float(d[c + 3]));
    }
  }
  __syncthreads();
  if (wid == 0) tmem_dealloc(tmem, 128);

#else  // ------------- FFMA fallback (non-sm_103a pass; still correct) -------
  extern __shared__ char smemraw[];
  float* sA = (float*)smemraw;
  float* sB = sA + 16 * 128;
  const int K = DM, N = QKV_N;
  const int tid = threadIdx.x;
  const int tx = tid & 15, ty = tid >> 4;
  const int row0 = blockIdx.y * 128;
  const int col0 = blockIdx.x * 128;

  float acc[8][8];
#pragma unroll
  for (int r = 0; r < 8; r++)
#pragma unroll
    for (int c = 0; c < 8; c++) acc[r][c] = 0.f;

  for (int kk = 0; kk < K; kk += 16) {
#pragma unroll
    for (int it = 0; it < 2; it++) {
      int e = tid + it * 256;
      int ar = e >> 2;
      int ac = (e & 3) * 4;
      float4 a4 = *(const float4*)(X + (size_t)(row0 + ar) * K + kk + ac);
      sA[(ac + 0) * 128 + ar] = a4.x;
      sA[(ac + 1) * 128 + ar] = a4.y;
      sA[(ac + 2) * 128 + ar] = a4.z;
      sA[(ac + 3) * 128 + ar] = a4.w;
    }
#pragma unroll
    for (int it = 0; it < 2; it++) {
      int e = tid + it * 256;
      int br = e >> 5;
      int bc = (e & 31) * 4;
      *(float4*)&sB[br * 128 + bc] = *(const float4*)(W + (size_t)(kk + br) * N + col0 + bc);
    }
    __syncthreads();
#pragma unroll
    for (int k = 0; k < 16; k++) {
      float ar[8], bc[8];
      *(float4*)&ar[0] = *(float4*)&sA[k * 128 + ty * 8];
      *(float4*)&ar[4] = *(float4*)&sA[k * 128 + ty * 8 + 4];
      *(float4*)&bc[0] = *(float4*)&sB[k * 128 + tx * 8];
      *(float4*)&bc[4] = *(float4*)&sB[k * 128 + tx * 8 + 4];
#pragma unroll
      for (int r = 0; r < 8; r++)
#pragma unroll
        for (int c = 0; c < 8; c++) acc[r][c] += ar[r] * bc[c];
    }
    __syncthreads();
  }
#pragma unroll
  for (int r = 0; r < 8; r++) {
    float* dst = g_qkv + (size_t)(row0 + ty * 8 + r) * QKV_N + col0 + tx * 8;
    *(float4*)dst       = make_float4(acc[r][0], acc[r][1], acc[r][2], acc[r][3]);
    *(float4*)(dst + 4) = make_float4(acc[r][4], acc[r][5], acc[r][6], acc[r][7]);
  }
#endif
}

// ===========================================================================
// Kernel: fused score. 128x64 tile, 256 threads, blocked 8x4 per thread,
// scalar FMA with LDS.128 operands (144B LDS per 32 outputs per d).
// Bands are 191 wide (row span 128), d-chunked (DCH=16).
// attn_score = (AC + BD + E)/8 + prev -> prev_out   (FROZEN: R13 best)
// ===========================================================================
namespace {
constexpr int DCH     = 16;
constexpr int BSTR    = 192;   // band row stride (191 used)
constexpr int SC_SMEM = (64 * 128 + 64 * 64 + 2 * DCH * BSTR) * 4;  // 73728 B
}

__global__ __launch_bounds__(256) void k_score(const float* __restrict__ rrb,
                                               const float* __restrict__ rwb,
                                               const float* __restrict__ relpos,
                                               const float* __restrict__ prev,
                                               const int* __restrict__ skip,
                                               float* __restrict__ prev_out) {
  extern __shared__ float smemf[];
  float* sQT = smemf;               // [64 d][128 r]
  float* sKT = sQT + 64 * 128;      // [64 d][64 c]
  float* sRq = sKT + 64 * 64;       // [DCH][BSTR] band chunk for BD (191 used)
  float* sRe = sRq + DCH * BSTR;    // [DCH][BSTR] band chunk for E
  __shared__ float cK[64];          // rrb . k_j
  __shared__ float cRq[BSTR];       // rwb . R_t (191 used), accumulated

  const int bh = blockIdx.z;
  const int b = bh >> 4, h = bh & 15;
  const int tid = threadIdx.x;
  const int tx = tid & 15, ty = tid >> 4;
  const int i0 = blockIdx.y * 128;
  const int j0 = blockIdx.x * 64;

  const float* Qb = g_qkv + (size_t)(b * SEQ) * QKV_N + h * HD;
  const float* Kb = Qb + DM;

  // load Q tile (128 rows) transposed into smem (d-major)
#pragma unroll
  for (int it = 0; it < 8; it++) {
    int e = tid + it * 256;       // 128 rows x 16 float4
    int r = e & 127;
    int c = (e >> 7) * 4;
    float4 q4 = *(const float4*)(Qb + (size_t)(i0 + r) * QKV_N + c);
    sQT[(c + 0) * 128 + r] = q4.x;
    sQT[(c + 1) * 128 + r] = q4.y;
    sQT[(c + 2) * 128 + r] = q4.z;
    sQT[(c + 3) * 128 + r] = q4.w;
  }
  // load K tile (64 cols) transposed
#pragma unroll
  for (int it = 0; it < 4; it++) {
    int e = tid + it * 256;       // 64 rows x 16 float4
    int r = e & 63;
    int c = (e >> 6) * 4;
    float4 k4 = *(const float4*)(Kb + (size_t)(j0 + r) * QKV_N + c);
    sKT[(c + 0) * 64 + r] = k4.x;
    sKT[(c + 1) * 64 + r] = k4.y;
    sKT[(c + 2) * 64 + r] = k4.z;
    sKT[(c + 3) * 64 + r] = k4.w;
  }
  if (tid < BSTR) cRq[tid] = 0.f;
  __syncthreads();

  // rank-1 correction cK (needs full-K sKT)
  if (tid < 64) {
    float s = 0.f;
#pragma unroll
    for (int d = 0; d < 64; d++) s += rrb[h * HD + d] * sKT[d * 64 + tid];
    cK[tid] = s;
  }

  float acc[8][4];
#pragma unroll
  for (int r = 0; r < 8; r++)
#pragma unroll
    for (int c = 0; c < 4; c++) acc[r][c] = 0.f;

  // blocked tile: rows i0 + ty*8 + r (r<8), cols j0 + tx*4 + c (c<4)
  const int xq0 = tx * 4 - ty * 8 + 120;   // in [0, 180]
  const int xe0 = ty * 8 - tx * 4 + 60;    // in [0, 180]
  const int q0g = SEQ + (j0 - i0) - 127;   // global band starts, within [1,1023]
  const int u0g = SEQ + (i0 - j0) - 63;

  for (int chk = 0; chk < 64 / DCH; chk++) {
    const int d0 = chk * DCH;
    // fill band chunks (191 of BSTR used)
    for (int e = tid; e < DCH * BSTR; e += 256) {
      int dl = e / BSTR, x = e - dl * BSTR;
      if (x < 191) {
        sRq[dl * BSTR + x] = relpos[(size_t)(d0 + dl) * P2 + q0g + x];
        sRe[dl * BSTR + x] = relpos[(size_t)(d0 + dl) * P2 + u0g + x];
      }
    }
    __syncthreads();

    // accumulate cRq partial for this chunk
    if (tid < 191) {
      float s = 0.f;
#pragma unroll
      for (int dl = 0; dl < DCH; dl++)
        s += rwb[h * HD + d0 + dl] * sRq[dl * BSTR + tid];
      cRq[tid] += s;
    }

#pragma unroll
    for (int dl = 0; dl < DCH; dl++) {
      const int d = d0 + dl;
      float a[8], bb[4], rq[12], re[12];
      *(float4*)&a[0]  = *(float4*)&sQT[d * 128 + ty * 8];
      *(float4*)&a[4]  = *(float4*)&sQT[d * 128 + ty * 8 + 4];
      *(float4*)&bb[0] = *(float4*)&sKT[d * 64 + tx * 4];
      *(float4*)&rq[0] = *(float4*)&sRq[dl * BSTR + xq0];
      *(float4*)&rq[4] = *(float4*)&sRq[dl * BSTR + xq0 + 4];
      *(float4*)&rq[8] = *(float4*)&sRq[dl * BSTR + xq0 + 8];
      *(float4*)&re[0] = *(float4*)&sRe[dl * BSTR + xe0];
      *(float4*)&re[4] = *(float4*)&sRe[dl * BSTR + xe0 + 4];
      *(float4*)&re[8] = *(float4*)&sRe[dl * BSTR + xe0 + 8];
#pragma unroll
      for (int r = 0; r < 8; r++)
#pragma unroll
        for (int c = 0; c < 4; c++)
          acc[r][c] += a[r] * bb[c] + a[r] * rq[c - r + 7] + bb[c] * re[r - c + 3];
    }
    __syncthreads();
  }

  const int sk = *skip;
  const float* prevb = prev + (size_t)bh * SEQ * SEQ;
  float* outb = prev_out + (size_t)bh * SEQ * SEQ;

#pragma unroll
  for (int r = 0; r < 8; r++) {
    const int i = i0 + ty * 8 + r;
    const int j = j0 + tx * 4;
    float4 p = make_float4(0.f, 0.f, 0.f, 0.f);
    if (sk) p = *(const float4*)(prevb + (size_t)i * SEQ + j);
    float4 o;
    o.x = (acc[r][0] + cK[tx * 4 + 0] + cRq[xq0 + 7 + 0 - r]) * 0.125f + p.x;
    o.y = (acc[r][1] + cK[tx * 4 + 1] + cRq[xq0 + 7 + 1 - r]) * 0.125f + p.y;
    o.z = (acc[r][2] + cK[tx * 4 + 2] + cRq[xq0 + 7 + 2 - r]) * 0.125f + p.z;
    o.w = (acc[r][3] + cK[tx * 4 + 3] + cRq[xq0 + 7 + 3 - r]) * 0.125f + p.w;
    *(float4*)(outb + (size_t)i * SEQ + j) = o;
  }
}

// ===========================================================================
// Kernel: out = softmax(S) @ V. 64 rows/block, 4x4 tile.
// Softmax: FUSED load+exp+sum, NO max subtraction (scores bounded ~12; exp
// and row sums are ~30 orders of magnitude below fp32 overflow; softmax
// without max is mathematically identical).
// sm_103a path: packed f32x2 FMAs over d-pairs, V stored d-interleaved.
// ===========================================================================
namespace {
constexpr int ROWS_AV   = 64;
constexpr int SS_STRIDE = 516;
constexpr int SMEM_AV   = (ROWS_AV * SS_STRIDE + 64 * 64) * 4;  // 148480 B
}

__global__ __launch_bounds__(256) void k_av(const float* __restrict__ Sglob,
                                            float* __restrict__ Out) {
  extern __shared__ float smemf[];
  float* sS = smemf;
  float* sV = smemf + ROWS_AV * SS_STRIDE;   // f32x2 path: [32 kp][64 c][2]
  __shared__ float sSum[ROWS_AV];

  const int bh = blockIdx.y;
  const int b = bh >> 4, h = bh & 15;
  const int row0 = blockIdx.x * ROWS_AV;
  const int tid = threadIdx.x;
  const int tx = tid & 15, ty = tid >> 4;
  const float* Sb = Sglob + ((size_t)bh * SEQ + row0) * SEQ;

  // fused: global load -> exp -> smem store + row-sum (warp w owns rows 8w..8w+7)
  {
    const int warp = tid >> 5, lane = tid & 31;
#pragma unroll
    for (int rr = 0; rr < 8; rr++) {
      const int row = warp * 8 + rr;
      const float* src = Sb + (size_t)row * SEQ;
      float* srow = sS + row * SS_STRIDE;
      float sum = 0.f;
#pragma unroll
      for (int it = 0; it < 4; it++) {
        const int c = lane * 4 + it * 128;
        float4 v = *(const float4*)(src + c);
        v.x = __expf(v.x); v.y = __expf(v.y);
        v.z = __expf(v.z); v.w = __expf(v.w);
        *(float4*)&srow[c] = v;
        sum += (v.x + v.y) + (v.z + v.w);
      }
#pragma unroll
      for (int o = 16; o > 0; o >>= 1) sum += __shfl_xor_sync(0xffffffffu, sum, o);
      if (lane == 0) sSum[row] = sum;
    }
  }
  __syncthreads();

  const float* Vb = g_qkv + (size_t)(b * SEQ) * QKV_N + 2 * DM + h * HD;

#if HAS_TCGEN05
  // ---- packed f32x2 PV: accumulate even-d in lane0, odd-d in lane1 ----
  ull acc2[4][4];
#pragma unroll
  for (int r = 0; r < 4; r++)
#pragma unroll
    for (int c = 0; c < 4; c++) acc2[r][c] = 0ull;

  for (int kc = 0; kc < SEQ; kc += 64) {
    __syncthreads();
    // fill V interleaved: sV[kp*128 + 2c + par] = V[kc + 2kp + par][c]
#pragma unroll
    for (int it = 0; it < 8; it++) {
      int e = tid + it * 256;     // 2048 tasks: kp = e>>6, c = e&63
      int kp = e >> 6;
      int c  = e & 63;
      float v0 = Vb[(size_t)(kc + 2 * kp) * QKV_N + c];
      float v1 = Vb[(size_t)(kc + 2 * kp + 1) * QKV_N + c];
      *(float2*)&sV[kp * 128 + 2 * c] = make_float2(v0, v1);
    }
    __syncthreads();
#pragma unroll 8
    for (int kp = 0; kp < 32; kp++) {
      ull p2[4], v2[4];
#pragma unroll
      for (int r = 0; r < 4; r++)
        p2[r] = *(const ull*)&sS[(ty + 16 * r) * SS_STRIDE + kc + 2 * kp];
#pragma unroll
      for (int c = 0; c < 4; c++)
        v2[c] = *(const ull*)&sV[kp * 128 + (tx + 16 * c) * 2];
#pragma unroll
      for (int r = 0; r < 4; r++)
#pragma unroll
        for (int c = 0; c < 4; c++) ffma2(acc2[r][c], p2[r], v2[c]);
    }
  }

#pragma unroll
  for (int r = 0; r < 4; r++) {
    const float inv = 1.f / sSum[ty + 16 * r];
    float* dst = Out + ((size_t)b * SEQ + row0 + ty + 16 * r) * DM + h * HD + tx;
#pragma unroll
    for (int c = 0; c < 4; c++) {
      float lo = __uint_as_float((uint32_t)(acc2[r][c] & 0xffffffffull));
      float hi = __uint_as_float((uint32_t)(acc2[r][c] >> 32));
      dst[16 * c] = (lo + hi) * inv;
    }
  }

#else
  // ---- scalar fallback (non-sm_103a pass) ----
  float acc[4][4];
#pragma unroll
  for (int r = 0; r < 4; r++)
#pragma unroll
    for (int c = 0; c < 4; c++) acc[r][c] = 0.f;

  for (int kc = 0; kc < SEQ; kc += 64) {
    __syncthreads();
#pragma unroll
    for (int it = 0; it < 4; it++) {
      int e = tid + it * 256;
      int kk = e >> 4;
      int c = (e & 15) * 4;
      *(float4*)&sV[kk * 64 + c] = *(const float4*)(Vb + (size_t)(kc + kk) * QKV_N + c);
    }
    __syncthreads();
#pragma unroll 8
    for (int kk = 0; kk < 64; kk++) {
      float p[4], v[4];
#pragma unroll
      for (int r = 0; r < 4; r++) p[r] = sS[(ty + 16 * r) * SS_STRIDE + kc + kk];
#pragma unroll
      for (int c = 0; c < 4; c++) v[c] = sV[kk * 64 + tx + 16 * c];
#pragma unroll
      for (int r = 0; r < 4; r++)
#pragma unroll
        for (int c = 0; c < 4; c++) acc[r][c] += p[r] * v[c];
    }
  }

#pragma unroll
  for (int r = 0; r < 4; r++) {
    const float inv = 1.f / sSum[ty + 16 * r];
    float* dst = Out + ((size_t)b * SEQ + row0 + ty + 16 * r) * DM + h * HD + tx;
#pragma unroll
    for (int c = 0; c < 4; c++) dst[16 * c] = acc[r][c] * inv;
  }
#endif
}

// ---------------------------------------------------------------------------
extern "C" void kernel_launch(void* const* d_in, const int* in_sizes, int n_in,
                              void* d_out, int out_size) {
  const float* x      = (const float*)d_in[0];
  const float* prev   = (const float*)d_in[1];
  const float* Wqkv   = (const float*)d_in[2];
  const float* rrb    = (const float*)d_in[3];
  const float* rwb    = (const float*)d_in[4];
  const float* relpos = (const float*)d_in[5];
  const int*   skip   = (const int*)d_in[6];

  float* out      = (float*)d_out;                       // (8,512,1024)
  float* prev_out = out + (size_t)BATCH * SEQ * DM;      // (8,16,512,512)

  k_convA<<<(MROWS * DM / 4) / 256, 256>>>(x);
  k_convB<<<dim3(QKV_N / 32, DM / 32), 256>>>(Wqkv);

  cudaFuncSetAttribute(k_qkv_mma, cudaFuncAttributeMaxDynamicSharedMemorySize, QSMEM);
  k_qkv_mma<<<dim3(QKV_N / 128, MROWS / 128), 256, QSMEM>>>(x, Wqkv);

  cudaFuncSetAttribute(k_score, cudaFuncAttributeMaxDynamicSharedMemorySize, SC_SMEM);
  dim3 g3(SEQ / 64, SEQ / 128, BH);                      // (8, 4, 128)
  k_score<<<g3, 256, SC_SMEM>>>(rrb, rwb, relpos, prev, skip, prev_out);

  cudaFuncSetAttribute(k_av, cudaFuncAttributeMaxDynamicSharedMemorySize, SMEM_AV);
  dim3 g4(SEQ / ROWS_AV, BH);                            // (8, 128)
  k_av<<<g4, 256, SMEM_AV>>>(prev_out, out);
}

// round 15
// speedup vs baseline: 1.7067x; 1.0720x over previous
#include <cuda_runtime.h>
#include <cuda_bf16.h>
#include <cstdint>

// ---------------------------------------------------------------------------
// RelativeMultiHeadAttn (Transformer-XL style) forward.
//
// qkv = x @ Wqkv via tcgen05 bf16 split-precision GEMM (K concat trick):
//   A2 = [Xhi | Xlo | Xhi]  (4096 x 3072 bf16, K-major)
//   B2 = [Whi | Whi | Wlo]^T (3072 x 3072 bf16, K-major)
//   qkv = A2 @ B2^T  accumulated fp32 in TMEM  ==  x@W up to ~2^-18 residual.
// R15: 128x256 output tiles (was 128x128) -> 25% less L2 traffic (LTS-bound).
// tcgen05 / f32x2 bodies guarded for the sm_103a arch-specific pass; the
// plain compute_103 pass compiles scalar fp32 fallbacks.
//
// score: 128x64 tiles, blocked 8x4/thread, scalar FMA + LDS.128 (80% of the
// scalar-FFMA floor; FROZEN). Band trick:
//   BD_shift[i,j] = (q_i + r_w) . R[:, L + j - i]
//   E_term[i,j]   = k_j . R[:, L + i - j]
// av: fused load+exp+sum softmax (no max; scores bounded ~12) + PV with
// packed f32x2 FMAs over d-pairs. (FROZEN)
// ---------------------------------------------------------------------------

namespace {
constexpr int BATCH = 8;
constexpr int NH    = 16;
constexpr int SEQ   = 512;
constexpr int DM    = 1024;
constexpr int HD    = 64;
constexpr int P2    = 2 * SEQ;      // 1024
constexpr int BH    = BATCH * NH;   // 128
constexpr int QKV_N = 3 * DM;       // 3072
constexpr int MROWS = BATCH * SEQ;  // 4096
constexpr int KTOT  = 3 * DM;       // 3072 (split-K concat)
constexpr int CH    = 64;           // K chunk (one SW128 atom column of bf16)
constexpr int NCH   = KTOT / CH;    // 48
constexpr int TN    = 256;          // qkv output tile N
}

// scratch (static device globals: allowed; no dynamic allocation)
__device__ float         g_qkv[(size_t)MROWS * QKV_N];    // 50 MB fp32
__device__ __nv_bfloat16 g_A2[(size_t)MROWS * KTOT];      // 25 MB
__device__ __nv_bfloat16 g_B2[(size_t)QKV_N * KTOT];      // 19 MB

// Feature gate: true only in the sm_103a (arch-specific) device pass.
#ifndef __CUDA_ARCH_SPECIFIC__
#define __CUDA_ARCH_SPECIFIC__ 0
#endif
#if !defined(__CUDA_ARCH__) || defined(__CUDA_ARCH_FEAT_SM103_ALL) || \
    (__CUDA_ARCH_SPECIFIC__ == 1030)
#define HAS_TCGEN05 1
#else
#define HAS_TCGEN05 0
#endif

typedef unsigned long long ull;

// packed fp32x2 FMA: d.lo += a.lo*b.lo ; d.hi += a.hi*b.hi
#if HAS_TCGEN05
__device__ __forceinline__ void ffma2(ull& d, ull a, ull b) {
  asm("fma.rn.f32x2 %0, %1, %2, %0;" : "+l"(d) : "l"(a), "l"(b));
}
#else
__device__ __forceinline__ void ffma2(ull& d, ull a, ull b) {
  float dl = __uint_as_float((uint32_t)d),  dh = __uint_as_float((uint32_t)(d >> 32));
  float al = __uint_as_float((uint32_t)a),  ah = __uint_as_float((uint32_t)(a >> 32));
  float bl = __uint_as_float((uint32_t)b),  bh = __uint_as_float((uint32_t)(b >> 32));
  dl = fmaf(al, bl, dl);
  dh = fmaf(ah, bh, dh);
  d = (ull)__float_as_uint(dl) | ((ull)__float_as_uint(dh) << 32);
}
#endif

// ===========================================================================
// minimal sm_103a PTX helpers
// ===========================================================================
__device__ __forceinline__ uint32_t smem_u32(const void* p) {
  uint32_t a;
  asm("{ .reg .u64 t; cvta.to.shared.u64 t, %1; cvt.u32.u64 %0, t; }"
      : "=r"(a) : "l"(p));
  return a;
}
#if HAS_TCGEN05
__device__ __forceinline__ uint32_t elect_one() {
  uint32_t pred;
  asm volatile("{\n\t.reg .pred p;\n\telect.sync _|p, 0xFFFFFFFF;\n\t"
               "selp.b32 %0, 1, 0, p;\n\t}" : "=r"(pred));
  return pred;
}
__device__ __forceinline__ void mbar_init(uint32_t mbar, uint32_t cnt) {
  asm volatile("mbarrier.init.shared.b64 [%0], %1;" :: "r"(mbar), "r"(cnt) : "memory");
}
__device__ __forceinline__ void mbar_wait(uint32_t mbar, uint32_t parity) {
  asm volatile(
      "{\n\t.reg .pred P;\n\t"
      "WL_%=:\n\t"
      "mbarrier.try_wait.parity.acquire.cta.shared::cta.b64 P, [%0], %1, 0x989680;\n\t"
      "@P bra.uni WD_%=;\n\t"
      "bra.uni WL_%=;\n\t"
      "WD_%=:\n\t}"
      :: "r"(mbar), "r"(parity) : "memory");
}
__device__ __forceinline__ void tmem_alloc(uint32_t smem_dst, uint32_t ncols) {
  asm volatile("tcgen05.alloc.cta_group::1.sync.aligned.shared::cta.b32 [%0], %1;"
               :: "r"(smem_dst), "r"(ncols) : "memory");
}
__device__ __forceinline__ void tmem_relinq() {
  asm volatile("tcgen05.relinquish_alloc_permit.cta_group::1.sync.aligned;");
}
__device__ __forceinline__ void tmem_dealloc(uint32_t tmem, uint32_t ncols) {
  asm volatile("tcgen05.dealloc.cta_group::1.sync.aligned.b32 %0, %1;"
               :: "r"(tmem), "r"(ncols));
}
__device__ __forceinline__ void tcommit(uint32_t mbar) {
  asm volatile(
      "tcgen05.commit.cta_group::1.mbarrier::arrive::one.shared::cluster.b64 [%0];"
      :: "r"(mbar) : "memory");
}
__device__ __forceinline__ void fence_async_shared() {
  asm volatile("fence.proxy.async.shared::cta;" ::: "memory");
}
__device__ __forceinline__ void tfence_after() {
  asm volatile("tcgen05.fence::after_thread_sync;" ::: "memory");
}
__device__ __forceinline__ void mma_f16_ss(uint32_t d, uint64_t ad, uint64_t bd,
                                           uint32_t idesc, uint32_t en) {
  asm volatile(
      "{\n\t.reg .pred p;\n\tsetp.ne.u32 p, %5, 0;\n\t"
      "tcgen05.mma.cta_group::1.kind::f16 [%0], %1, %2, %3, {%4, %4, %4, %4}, p;\n\t}"
      :: "r"(d), "l"(ad), "l"(bd), "r"(idesc), "r"(0u), "r"(en) : "memory");
}
#define TC_LD_X32(r, addr)                                                      \
  asm volatile(                                                                 \
      "tcgen05.ld.sync.aligned.32x32b.x32.b32 "                                 \
      "{%0,%1,%2,%3,%4,%5,%6,%7,%8,%9,%10,%11,%12,%13,%14,%15,"                \
      "%16,%17,%18,%19,%20,%21,%22,%23,%24,%25,%26,%27,%28,%29,%30,%31}, [%32];" \
      : "=r"((r)[0]), "=r"((r)[1]), "=r"((r)[2]), "=r"((r)[3]),                 \
        "=r"((r)[4]), "=r"((r)[5]), "=r"((r)[6]), "=r"((r)[7]),                 \
        "=r"((r)[8]), "=r"((r)[9]), "=r"((r)[10]), "=r"((r)[11]),               \
        "=r"((r)[12]), "=r"((r)[13]), "=r"((r)[14]), "=r"((r)[15]),             \
        "=r"((r)[16]), "=r"((r)[17]), "=r"((r)[18]), "=r"((r)[19]),             \
        "=r"((r)[20]), "=r"((r)[21]), "=r"((r)[22]), "=r"((r)[23]),             \
        "=r"((r)[24]), "=r"((r)[25]), "=r"((r)[26]), "=r"((r)[27]),             \
        "=r"((r)[28]), "=r"((r)[29]), "=r"((r)[30]), "=r"((r)[31])              \
      : "r"(addr))
__device__ __forceinline__ void tc_wait_ld() {
  asm volatile("tcgen05.wait::ld.sync.aligned;" ::: "memory");
}
// SW128 K-major SMEM descriptor (LBO=1, SBO=64, version=1, layout=2)
__device__ __forceinline__ uint64_t smem_desc_sw128(uint32_t addr) {
  const uint64_t base = (uint64_t(2) << 61) | (uint64_t(1) << 46) |
                        (uint64_t(64) << 32) | (uint64_t(1) << 16);
  return base | ((uint64_t)(addr >> 4) & 0x3FFF);
}
#endif  // HAS_TCGEN05

// idesc: fp32 accum, bf16 x bf16, M=128, N=TN(=256)
namespace {
constexpr uint32_t IDESC =
    (1u << 4) | (1u << 7) | (1u << 10) | ((TN / 8u) << 17) | ((128u / 16) << 24);
}

// ===========================================================================
// Conversion kernels: fp32 -> split bf16 (hi/lo), B transposed to K-major
// ===========================================================================
__global__ __launch_bounds__(256) void k_convA(const float* __restrict__ X) {
  size_t i = (size_t)blockIdx.x * 256 + threadIdx.x;  // quad index
  float4 v = ((const float4*)X)[i];
  size_t m = i >> 8;
  size_t q = (i & 255) * 4;

  __nv_bfloat162 h01 = __floats2bfloat162_rn(v.x, v.y);
  __nv_bfloat162 h23 = __floats2bfloat162_rn(v.z, v.w);
  float lx = v.x - __bfloat162float(h01.x);
  float ly = v.y - __bfloat162float(h01.y);
  float lz = v.z - __bfloat162float(h23.x);
  float lw = v.w - __bfloat162float(h23.y);
  __nv_bfloat162 l01 = __floats2bfloat162_rn(lx, ly);
  __nv_bfloat162 l23 = __floats2bfloat162_rn(lz, lw);

  uint2 uh, ul;
  uh.x = *(uint32_t*)&h01; uh.y = *(uint32_t*)&h23;
  ul.x = *(uint32_t*)&l01; ul.y = *(uint32_t*)&l23;

  __nv_bfloat16* row = g_A2 + m * KTOT;
  *(uint2*)(row + q)          = uh;
  *(uint2*)(row + DM + q)     = ul;
  *(uint2*)(row + 2 * DM + q) = uh;
}

__global__ __launch_bounds__(256) void k_convB(const float* __restrict__ W) {
  __shared__ float tile[32][33];
  const int n0 = blockIdx.x * 32;
  const int k0 = blockIdx.y * 32;
  const int tid = threadIdx.x;
#pragma unroll
  for (int it = 0; it < 4; it++) {
    int e = tid + it * 256;
    int kk = e >> 5, nn = e & 31;
    tile[kk][nn] = W[(size_t)(k0 + kk) * QKV_N + n0 + nn];
  }
  __syncthreads();
#pragma unroll
  for (int it = 0; it < 4; it++) {
    int e = tid + it * 256;
    int nn = e >> 5, kk = e & 31;
    float x = tile[kk][nn];
    __nv_bfloat16 hi = __float2bfloat16_rn(x);
    __nv_bfloat16 lo = __float2bfloat16_rn(x - __bfloat162float(hi));
    __nv_bfloat16* row = g_B2 + (size_t)(n0 + nn) * KTOT;
    row[k0 + kk]          = hi;
    row[DM + k0 + kk]     = hi;
    row[2 * DM + k0 + kk] = lo;
  }
}

// ===========================================================================
// Kernel: qkv = A2 @ B2^T via tcgen05. 128 x 256 output tile, K=3072 in
// 64-chunks, double-buffered smem, mbarrier backpressure, 256-col TMEM acc.
// ===========================================================================
namespace {
constexpr int ASTG  = 16384;                  // A stage bytes (128 x 64 bf16)
constexpr int BSTG  = TN * CH * 2;            // B stage bytes (256 x 64 bf16) = 32768
constexpr int QSMEM = 1024 + 2 * (ASTG + BSTG);  // 99328
}

__global__ __launch_bounds__(256) void k_qkv_mma(const float* __restrict__ X,
                                                 const float* __restrict__ W) {
#if HAS_TCGEN05
  extern __shared__ char smem[];
  const uint32_t sb = smem_u32(smem);
  const uint32_t TPTR  = sb;
  const uint32_t MBAR0 = sb + 16;
  const uint32_t MBAR1 = sb + 24;
  const uint32_t STAGE = sb + 1024;

  const int tid = threadIdx.x;
  const int wid = tid >> 5;

  if (wid == 0) tmem_alloc(TPTR, 256);
  if (tid == 0) { mbar_init(MBAR0, 1); mbar_init(MBAR1, 1); }
  __syncthreads();
  uint32_t tmem;
  asm volatile("ld.shared.b32 %0, [%1];" : "=r"(tmem) : "r"(TPTR));
  if (wid == 0) tmem_relinq();

  const int m0 = blockIdx.y * 128;
  const int n0 = blockIdx.x * TN;
  const __nv_bfloat16* Ag = g_A2 + (size_t)m0 * KTOT;
  const __nv_bfloat16* Bg = g_B2 + (size_t)n0 * KTOT;

  uint32_t ph0 = 0, ph1 = 0;
  for (int t = 0; t < NCH; t++) {
    const int p = t & 1;
    const uint32_t Abase = STAGE + p * (ASTG + BSTG);
    const uint32_t Bbase = Abase + ASTG;
    if (t >= 2) {
      if (p == 0) { mbar_wait(MBAR0, ph0); ph0 ^= 1; }
      else        { mbar_wait(MBAR1, ph1); ph1 ^= 1; }
    }
    const int kc = t * CH;
    // A: 128 rows x 64 bf16 = 1024 u4; B: 256 rows x 64 bf16 = 2048 u4
    uint4 av[4], bv[8];
#pragma unroll
    for (int it = 0; it < 4; it++) {
      int e = tid + it * 256;
      int r = e >> 3, sg = e & 7;
      av[it] = *(const uint4*)((const char*)(Ag + (size_t)r * KTOT + kc) + sg * 16);
    }
#pragma unroll
    for (int it = 0; it < 8; it++) {
      int e = tid + it * 256;
      int r = e >> 3, sg = e & 7;
      bv[it] = *(const uint4*)((const char*)(Bg + (size_t)r * KTOT + kc) + sg * 16);
    }
#pragma unroll
    for (int it = 0; it < 4; it++) {
      int e = tid + it * 256;
      int r = e >> 3, sg = e & 7;
      uint32_t off = r * 128 + sg * 16;
      uint32_t sw = off ^ ((off >> 3) & 0x70);
      *(uint4*)(smem + (Abase - sb) + sw) = av[it];
    }
#pragma unroll
    for (int it = 0; it < 8; it++) {
      int e = tid + it * 256;
      int r = e >> 3, sg = e & 7;
      uint32_t off = r * 128 + sg * 16;
      uint32_t sw = off ^ ((off >> 3) & 0x70);
      *(uint4*)(smem + (Bbase - sb) + sw) = bv[it];
    }
    __syncthreads();
    if (wid == 0) {
      if (elect_one()) {
        fence_async_shared();
        uint64_t ad = smem_desc_sw128(Abase);
        uint64_t bd = smem_desc_sw128(Bbase);
#pragma unroll
        for (int k = 0; k < 4; k++)
          mma_f16_ss(tmem, ad + k * 2, bd + k * 2, IDESC, (t > 0 || k > 0) ? 1u : 0u);
        tcommit(p == 0 ? MBAR0 : MBAR1);
      }
    }
  }
  mbar_wait(MBAR1, ph1);
  tfence_after();

  if (wid < 4) {
    const int lid = tid & 31;
    const int orow = m0 + wid * 32 + lid;
#pragma unroll
    for (int cb = 0; cb < TN; cb += 32) {
      uint32_t d[32];
      TC_LD_X32(d, tmem + cb);
      tc_wait_ld();
      float* dst = g_qkv + (size_t)orow * QKV_N + n0 + cb;
#pragma unroll
      for (int c = 0; c < 32; c += 4)
        *(float4*)(dst + c) = make_float4(__uint_as_float(d[c]),
                                          __uint_as_float(d[c + 1]),
                                          __uint_as_float(d[c + 2]),
                                          __uint_as_float(d[c + 3]));
    }
  }
  __syncthreads();
  if (wid == 0) tmem_dealloc(tmem, 256);

#else  // ------------- FFMA fallback (non-sm_103a pass; still correct) -------
  // 128x128 fp32 tiled GEMM from x/W directly (grid.x covers TN in 2 halves)
  extern __shared__ char smemraw[];
  float* sA = (float*)smemraw;
  float* sB = sA + 16 * 128;
  const int K = DM, N = QKV_N;
  const int tid = threadIdx.x;
  const int tx = tid & 15, ty = tid >> 4;
  const int row0 = blockIdx.y * 128;

  for (int half = 0; half < TN / 128; half++) {
    const int col0 = blockIdx.x * TN + half * 128;
    float acc[8][8];
#pragma unroll
    for (int r = 0; r < 8; r++)
#pragma unroll
      for (int c = 0; c < 8; c++) acc[r][c] = 0.f;

    for (int kk = 0; kk < K; kk += 16) {
      __syncthreads();
#pragma unroll
      for (int it = 0; it < 2; it++) {
        int e = tid + it * 256;
        int ar = e >> 2;
        int ac = (e & 3) * 4;
        float4 a4 = *(const float4*)(X + (size_t)(row0 + ar) * K + kk + ac);
        sA[(ac + 0) * 128 + ar] = a4.x;
        sA[(ac + 1) * 128 + ar] = a4.y;
        sA[(ac + 2) * 128 + ar] = a4.z;
        sA[(ac + 3) * 128 + ar] = a4.w;
      }
#pragma unroll
      for (int it = 0; it < 2; it++) {
        int e = tid + it * 256;
        int br = e >> 5;
        int bc = (e & 31) * 4;
        *(float4*)&sB[br * 128 + bc] = *(const float4*)(W + (size_t)(kk + br) * N + col0 + bc);
      }
      __syncthreads();
#pragma unroll
      for (int k = 0; k < 16; k++) {
        float ar[8], bc[8];
        *(float4*)&ar[0] = *(float4*)&sA[k * 128 + ty * 8];
        *(float4*)&ar[4] = *(float4*)&sA[k * 128 + ty * 8 + 4];
        *(float4*)&bc[0] = *(float4*)&sB[k * 128 + tx * 8];
        *(float4*)&bc[4] = *(float4*)&sB[k * 128 + tx * 8 + 4];
#pragma unroll
        for (int r = 0; r < 8; r++)
#pragma unroll
          for (int c = 0; c < 8; c++) acc[r][c] += ar[r] * bc[c];
      }
    }
#pragma unroll
    for (int r = 0; r < 8; r++) {
      float* dst = g_qkv + (size_t)(row0 + ty * 8 + r) * QKV_N + col0 + tx * 8;
      *(float4*)dst       = make_float4(acc[r][0], acc[r][1], acc[r][2], acc[r][3]);
      *(float4*)(dst + 4) = make_float4(acc[r][4], acc[r][5], acc[r][6], acc[r][7]);
    }
  }
#endif
}

// ===========================================================================
// Kernel: fused score. 128x64 tile, 256 threads, blocked 8x4 per thread,
// scalar FMA with LDS.128 operands. FROZEN (R13/R14 best: 425us, 80% of floor)
// ===========================================================================
namespace {
constexpr int DCH     = 16;
constexpr int BSTR    = 192;   // band row stride (191 used)
constexpr int SC_SMEM = (64 * 128 + 64 * 64 + 2 * DCH * BSTR) * 4;  // 73728 B
}

__global__ __launch_bounds__(256) void k_score(const float* __restrict__ rrb,
                                               const float* __restrict__ rwb,
                                               const float* __restrict__ relpos,
                                               const float* __restrict__ prev,
                                               const int* __restrict__ skip,
                                               float* __restrict__ prev_out) {
  extern __shared__ float smemf[];
  float* sQT = smemf;               // [64 d][128 r]
  float* sKT = sQT + 64 * 128;      // [64 d][64 c]
  float* sRq = sKT + 64 * 64;       // [DCH][BSTR] band chunk for BD (191 used)
  float* sRe = sRq + DCH * BSTR;    // [DCH][BSTR] band chunk for E
  __shared__ float cK[64];          // rrb . k_j
  __shared__ float cRq[BSTR];       // rwb . R_t (191 used), accumulated

  const int bh = blockIdx.z;
  const int b = bh >> 4, h = bh & 15;
  const int tid = threadIdx.x;
  const int tx = tid & 15, ty = tid >> 4;
  const int i0 = blockIdx.y * 128;
  const int j0 = blockIdx.x * 64;

  const float* Qb = g_qkv + (size_t)(b * SEQ) * QKV_N + h * HD;
  const float* Kb = Qb + DM;

  // load Q tile (128 rows) transposed into smem (d-major)
#pragma unroll
  for (int it = 0; it < 8; it++) {
    int e = tid + it * 256;       // 128 rows x 16 float4
    int r = e & 127;
    int c = (e >> 7) * 4;
    float4 q4 = *(const float4*)(Qb + (size_t)(i0 + r) * QKV_N + c);
    sQT[(c + 0) * 128 + r] = q4.x;
    sQT[(c + 1) * 128 + r] = q4.y;
    sQT[(c + 2) * 128 + r] = q4.z;
    sQT[(c + 3) * 128 + r] = q4.w;
  }
  // load K tile (64 cols) transposed
#pragma unroll
  for (int it = 0; it < 4; it++) {
    int e = tid + it * 256;       // 64 rows x 16 float4
    int r = e & 63;
    int c = (e >> 6) * 4;
    float4 k4 = *(const float4*)(Kb + (size_t)(j0 + r) * QKV_N + c);
    sKT[(c + 0) * 64 + r] = k4.x;
    sKT[(c + 1) * 64 + r] = k4.y;
    sKT[(c + 2) * 64 + r] = k4.z;
    sKT[(c + 3) * 64 + r] = k4.w;
  }
  if (tid < BSTR) cRq[tid] = 0.f;
  __syncthreads();

  // rank-1 correction cK (needs full-K sKT)
  if (tid < 64) {
    float s = 0.f;
#pragma unroll
    for (int d = 0; d < 64; d++) s += rrb[h * HD + d] * sKT[d * 64 + tid];
    cK[tid] = s;
  }

  float acc[8][4];
#pragma unroll
  for (int r = 0; r < 8; r++)
#pragma unroll
    for (int c = 0; c < 4; c++) acc[r][c] = 0.f;

  // blocked tile: rows i0 + ty*8 + r (r<8), cols j0 + tx*4 + c (c<4)
  const int xq0 = tx * 4 - ty * 8 + 120;   // in [0, 180]
  const int xe0 = ty * 8 - tx * 4 + 60;    // in [0, 180]
  const int q0g = SEQ + (j0 - i0) - 127;   // global band starts, within [1,1023]
  const int u0g = SEQ + (i0 - j0) - 63;

  for (int chk = 0; chk < 64 / DCH; chk++) {
    const int d0 = chk * DCH;
    // fill band chunks (191 of BSTR used)
    for (int e = tid; e < DCH * BSTR; e += 256) {
      int dl = e / BSTR, x = e - dl * BSTR;
      if (x < 191) {
        sRq[dl * BSTR + x] = relpos[(size_t)(d0 + dl) * P2 + q0g + x];
        sRe[dl * BSTR + x] = relpos[(size_t)(d0 + dl) * P2 + u0g + x];
      }
    }
    __syncthreads();

    // accumulate cRq partial for this chunk
    if (tid < 191) {
      float s = 0.f;
#pragma unroll
      for (int dl = 0; dl < DCH; dl++)
        s += rwb[h * HD + d0 + dl] * sRq[dl * BSTR + tid];
      cRq[tid] += s;
    }

#pragma unroll
    for (int dl = 0; dl < DCH; dl++) {
      const int d = d0 + dl;
      float a[8], bb[4], rq[12], re[12];
      *(float4*)&a[0]  = *(float4*)&sQT[d * 128 + ty * 8];
      *(float4*)&a[4]  = *(float4*)&sQT[d * 128 + ty * 8 + 4];
      *(float4*)&bb[0] = *(float4*)&sKT[d * 64 + tx * 4];
      *(float4*)&rq[0] = *(float4*)&sRq[dl * BSTR + xq0];
      *(float4*)&rq[4] = *(float4*)&sRq[dl * BSTR + xq0 + 4];
      *(float4*)&rq[8] = *(float4*)&sRq[dl * BSTR + xq0 + 8];
      *(float4*)&re[0] = *(float4*)&sRe[dl * BSTR + xe0];
      *(float4*)&re[4] = *(float4*)&sRe[dl * BSTR + xe0 + 4];
      *(float4*)&re[8] = *(float4*)&sRe[dl * BSTR + xe0 + 8];
#pragma unroll
      for (int r = 0; r < 8; r++)
#pragma unroll
        for (int c = 0; c < 4; c++)
          acc[r][c] += a[r] * bb[c] + a[r] * rq[c - r + 7] + bb[c] * re[r - c + 3];
    }
    __syncthreads();
  }

  const int sk = *skip;
  const float* prevb = prev + (size_t)bh * SEQ * SEQ;
  float* outb = prev_out + (size_t)bh * SEQ * SEQ;

#pragma unroll
  for (int r = 0; r < 8; r++) {
    const int i = i0 + ty * 8 + r;
    const int j = j0 + tx * 4;
    float4 p = make_float4(0.f, 0.f, 0.f, 0.f);
    if (sk) p = *(const float4*)(prevb + (size_t)i * SEQ + j);
    float4 o;
    o.x = (acc[r][0] + cK[tx * 4 + 0] + cRq[xq0 + 7 + 0 - r]) * 0.125f + p.x;
    o.y = (acc[r][1] + cK[tx * 4 + 1] + cRq[xq0 + 7 + 1 - r]) * 0.125f + p.y;
    o.z = (acc[r][2] + cK[tx * 4 + 2] + cRq[xq0 + 7 + 2 - r]) * 0.125f + p.z;
    o.w = (acc[r][3] + cK[tx * 4 + 3] + cRq[xq0 + 7 + 3 - r]) * 0.125f + p.w;
    *(float4*)(outb + (size_t)i * SEQ + j) = o;
  }
}

// ===========================================================================
// Kernel: out = softmax(S) @ V. 64 rows/block, 4x4 tile.
// Fused load+exp+sum softmax (no max). FROZEN (R14).
// ===========================================================================
namespace {
constexpr int ROWS_AV   = 64;
constexpr int SS_STRIDE = 516;
constexpr int SMEM_AV   = (ROWS_AV * SS_STRIDE + 64 * 64) * 4;  // 148480 B
}

__global__ __launch_bounds__(256) void k_av(const float* __restrict__ Sglob,
                                            float* __restrict__ Out) {
  extern __shared__ float smemf[];
  float* sS = smemf;
  float* sV = smemf + ROWS_AV * SS_STRIDE;   // f32x2 path: [32 kp][64 c][2]
  __shared__ float sSum[ROWS_AV];

  const int bh = blockIdx.y;
  const int b = bh >> 4, h = bh & 15;
  const int row0 = blockIdx.x * ROWS_AV;
  const int tid = threadIdx.x;
  const int tx = tid & 15, ty = tid >> 4;
  const float* Sb = Sglob + ((size_t)bh * SEQ + row0) * SEQ;

  // fused: global load -> exp -> smem store + row-sum (warp w owns rows 8w..8w+7)
  {
    const int warp = tid >> 5, lane = tid & 31;
#pragma unroll
    for (int rr = 0; rr < 8; rr++) {
      const int row = warp * 8 + rr;
      const float* src = Sb + (size_t)row * SEQ;
      float* srow = sS + row * SS_STRIDE;
      float sum = 0.f;
#pragma unroll
      for (int it = 0; it < 4; it++) {
        const int c = lane * 4 + it * 128;
        float4 v = *(const float4*)(src + c);
        v.x = __expf(v.x); v.y = __expf(v.y);
        v.z = __expf(v.z); v.w = __expf(v.w);
        *(float4*)&srow[c] = v;
        sum += (v.x + v.y) + (v.z + v.w);
      }
#pragma unroll
      for (int o = 16; o > 0; o >>= 1) sum += __shfl_xor_sync(0xffffffffu, sum, o);
      if (lane == 0) sSum[row] = sum;
    }
  }
  __syncthreads();

  const float* Vb = g_qkv + (size_t)(b * SEQ) * QKV_N + 2 * DM + h * HD;

#if HAS_TCGEN05
  // ---- packed f32x2 PV: accumulate even-d in lane0, odd-d in lane1 ----
  ull acc2[4][4];
#pragma unroll
  for (int r = 0; r < 4; r++)
#pragma unroll
    for (int c = 0; c < 4; c++) acc2[r][c] = 0ull;

  for (int kc = 0; kc < SEQ; kc += 64) {
    __syncthreads();
    // fill V interleaved: sV[kp*128 + 2c + par] = V[kc + 2kp + par][c]
#pragma unroll
    for (int it = 0; it < 8; it++) {
      int e = tid + it * 256;     // 2048 tasks: kp = e>>6, c = e&63
      int kp = e >> 6;
      int c  = e & 63;
      float v0 = Vb[(size_t)(kc + 2 * kp) * QKV_N + c];
      float v1 = Vb[(size_t)(kc + 2 * kp + 1) * QKV_N + c];
      *(float2*)&sV[kp * 128 + 2 * c] = make_float2(v0, v1);
    }
    __syncthreads();
#pragma unroll 8
    for (int kp = 0; kp < 32; kp++) {
      ull p2[4], v2[4];
#pragma unroll
      for (int r = 0; r < 4; r++)
        p2[r] = *(const ull*)&sS[(ty + 16 * r) * SS_STRIDE + kc + 2 * kp];
#pragma unroll
      for (int c = 0; c < 4; c++)
        v2[c] = *(const ull*)&sV[kp * 128 + (tx + 16 * c) * 2];
#pragma unroll
      for (int r = 0; r < 4; r++)
#pragma unroll
        for (int c = 0; c < 4; c++) ffma2(acc2[r][c], p2[r], v2[c]);
    }
  }

#pragma unroll
  for (int r = 0; r < 4; r++) {
    const float inv = 1.f / sSum[ty + 16 * r];
    float* dst = Out + ((size_t)b * SEQ + row0 + ty + 16 * r) * DM + h * HD + tx;
#pragma unroll
    for (int c = 0; c < 4; c++) {
      float lo = __uint_as_float((uint32_t)(acc2[r][c] & 0xffffffffull));
      float hi = __uint_as_float((uint32_t)(acc2[r][c] >> 32));
      dst[16 * c] = (lo + hi) * inv;
    }
  }

#else
  // ---- scalar fallback (non-sm_103a pass) ----
  float acc[4][4];
#pragma unroll
  for (int r = 0; r < 4; r++)
#pragma unroll
    for (int c = 0; c < 4; c++) acc[r][c] = 0.f;

  for (int kc = 0; kc < SEQ; kc += 64) {
    __syncthreads();
#pragma unroll
    for (int it = 0; it < 4; it++) {
      int e = tid + it * 256;
      int kk = e >> 4;
      int c = (e & 15) * 4;
      *(float4*)&sV[kk * 64 + c] = *(const float4*)(Vb + (size_t)(kc + kk) * QKV_N + c);
    }
    __syncthreads();
#pragma unroll 8
    for (int kk = 0; kk < 64; kk++) {
      float p[4], v[4];
#pragma unroll
      for (int r = 0; r < 4; r++) p[r] = sS[(ty + 16 * r) * SS_STRIDE + kc + kk];
#pragma unroll
      for (int c = 0; c < 4; c++) v[c] = sV[kk * 64 + tx + 16 * c];
#pragma unroll
      for (int r = 0; r < 4; r++)
#pragma unroll
        for (int c = 0; c < 4; c++) acc[r][c] += p[r] * v[c];
    }
  }

#pragma unroll
  for (int r = 0; r < 4; r++) {
    const float inv = 1.f / sSum[ty + 16 * r];
    float* dst = Out + ((size_t)b * SEQ + row0 + ty + 16 * r) * DM + h * HD + tx;
#pragma unroll
    for (int c = 0; c < 4; c++) dst[16 * c] = acc[r][c] * inv;
  }
#endif
}

// ---------------------------------------------------------------------------
extern "C" void kernel_launch(void* const* d_in, const int* in_sizes, int n_in,
                              void* d_out, int out_size) {
  const float* x      = (const float*)d_in[0];
  const float* prev   = (const float*)d_in[1];
  const float* Wqkv   = (const float*)d_in[2];
  const float* rrb    = (const float*)d_in[3];
  const float* rwb    = (const float*)d_in[4];
  const float* relpos = (const float*)d_in[5];
  const int*   skip   = (const int*)d_in[6];

  float* out      = (float*)d_out;                       // (8,512,1024)
  float* prev_out = out + (size_t)BATCH * SEQ * DM;      // (8,16,512,512)

  k_convA<<<(MROWS * DM / 4) / 256, 256>>>(x);
  k_convB<<<dim3(QKV_N / 32, DM / 32), 256>>>(Wqkv);

  cudaFuncSetAttribute(k_qkv_mma, cudaFuncAttributeMaxDynamicSharedMemorySize, QSMEM);
  k_qkv_mma<<<dim3(QKV_N / TN, MROWS / 128), 256, QSMEM>>>(x, Wqkv);

  cudaFuncSetAttribute(k_score, cudaFuncAttributeMaxDynamicSharedMemorySize, SC_SMEM);
  dim3 g3(SEQ / 64, SEQ / 128, BH);                      // (8, 4, 128)
  k_score<<<g3, 256, SC_SMEM>>>(rrb, rwb, relpos, prev, skip, prev_out);

  cudaFuncSetAttribute(k_av, cudaFuncAttributeMaxDynamicSharedMemorySize, SMEM_AV);
  dim3 g4(SEQ / ROWS_AV, BH);                            // (8, 128)
  k_av<<<g4, 256, SMEM_AV>>>(prev_out, out);
}

// round 16
// speedup vs baseline: 2.0537x; 1.2033x over previous
#include <cuda_runtime.h>
#include <cuda_bf16.h>
#include <cstdint>

// ---------------------------------------------------------------------------
// RelativeMultiHeadAttn forward. R16: score on tcgen05.
// qkv: split-bf16 K-concat GEMM, 128x256 tiles (R15).
// score tile (bh, i0:128, j0:64): three GEMMs share TMEM (64+192+256=512):
//   AC=Q.K^T; G=Q.Rq^T (BD[i,j]=G[i,jj-il+127]+rw.Rq); H=K128.Re^T
//   (E[i,j]=H[jloc, il-jj+63 local]). Split precision via chunk pairing.
// Q2/K2/R2 pre-swizzled split bf16; R2 phase (t-1)&7 (band starts == 1 mod 8).
// av: fused exp softmax + f32x2 PV (frozen).
// ---------------------------------------------------------------------------

namespace {
constexpr int BATCH = 8;
constexpr int NH    = 16;
constexpr int SEQ   = 512;
constexpr int DM    = 1024;
constexpr int HD    = 64;
constexpr int P2    = 2 * SEQ;
constexpr int BH    = BATCH * NH;
constexpr int QKV_N = 3 * DM;
constexpr int MROWS = BATCH * SEQ;
constexpr int KTOT  = 3 * DM;
constexpr int CH    = 64;
constexpr int NCH   = KTOT / CH;
constexpr int TN    = 256;
constexpr int R2R   = 1040;          // R2 rows (1024 data + pad)
}

__device__ float         g_qkv[(size_t)MROWS * QKV_N];
__device__ __nv_bfloat16 g_A2[(size_t)MROWS * KTOT];
__device__ __nv_bfloat16 g_B2[(size_t)QKV_N * KTOT];
__device__ unsigned char g_Q2[(size_t)BH * 2 * 512 * 128];  // [bh][ch][row][128B]
__device__ unsigned char g_K2[(size_t)BH * 2 * 512 * 128];
__device__ unsigned char g_R2[(size_t)2 * R2R * 128];       // [ch][t][128B]

#ifndef __CUDA_ARCH_SPECIFIC__
#define __CUDA_ARCH_SPECIFIC__ 0
#endif
#if !defined(__CUDA_ARCH__) || defined(__CUDA_ARCH_FEAT_SM103_ALL) || \
    (__CUDA_ARCH_SPECIFIC__ == 1030)
#define HAS_TCGEN05 1
#else
#define HAS_TCGEN05 0
#endif

typedef unsigned long long ull;

__device__ __forceinline__ uint32_t smem_u32(const void* p) {
  uint32_t a;
  asm("{ .reg .u64 t; cvta.to.shared.u64 t, %1; cvt.u32.u64 %0, t; }"
      : "=r"(a) : "l"(p));
  return a;
}

#if HAS_TCGEN05
__device__ __forceinline__ void ffma2(ull& d, ull a, ull b) {
  asm("fma.rn.f32x2 %0, %1, %2, %0;" : "+l"(d) : "l"(a), "l"(b));
}
__device__ __forceinline__ uint32_t elect_one() {
  uint32_t pred;
  asm volatile("{\n\t.reg .pred p;\n\telect.sync _|p, 0xFFFFFFFF;\n\t"
               "selp.b32 %0, 1, 0, p;\n\t}" : "=r"(pred));
  return pred;
}
__device__ __forceinline__ void mbar_init(uint32_t mbar, uint32_t cnt) {
  asm volatile("mbarrier.init.shared.b64 [%0], %1;" :: "r"(mbar), "r"(cnt) : "memory");
}
__device__ __forceinline__ void mbar_wait(uint32_t mbar, uint32_t parity) {
  asm volatile(
      "{\n\t.reg .pred P;\n\tWL_%=:\n\t"
      "mbarrier.try_wait.parity.acquire.cta.shared::cta.b64 P, [%0], %1, 0x989680;\n\t"
      "@P bra.uni WD_%=;\n\tbra.uni WL_%=;\n\tWD_%=:\n\t}"
      :: "r"(mbar), "r"(parity) : "memory");
}
__device__ __forceinline__ void tmem_alloc(uint32_t smem_dst, uint32_t ncols) {
  asm volatile("tcgen05.alloc.cta_group::1.sync.aligned.shared::cta.b32 [%0], %1;"
               :: "r"(smem_dst), "r"(ncols) : "memory");
}
__device__ __forceinline__ void tmem_relinq() {
  asm volatile("tcgen05.relinquish_alloc_permit.cta_group::1.sync.aligned;");
}
__device__ __forceinline__ void tmem_dealloc(uint32_t tmem, uint32_t ncols) {
  asm volatile("tcgen05.dealloc.cta_group::1.sync.aligned.b32 %0, %1;"
               :: "r"(tmem), "r"(ncols));
}
__device__ __forceinline__ void tcommit(uint32_t mbar) {
  asm volatile(
      "tcgen05.commit.cta_group::1.mbarrier::arrive::one.shared::cluster.b64 [%0];"
      :: "r"(mbar) : "memory");
}
__device__ __forceinline__ void fence_async_shared() {
  asm volatile("fence.proxy.async.shared::cta;" ::: "memory");
}
__device__ __forceinline__ void tfence_after() {
  asm volatile("tcgen05.fence::after_thread_sync;" ::: "memory");
}
__device__ __forceinline__ void mma_f16_ss(uint32_t d, uint64_t ad, uint64_t bd,
                                           uint32_t idesc, uint32_t en) {
  asm volatile(
      "{\n\t.reg .pred p;\n\tsetp.ne.u32 p, %5, 0;\n\t"
      "tcgen05.mma.cta_group::1.kind::f16 [%0], %1, %2, %3, {%4, %4, %4, %4}, p;\n\t}"
      :: "r"(d), "l"(ad), "l"(bd), "r"(idesc), "r"(0u), "r"(en) : "memory");
}
#define TC_LD_X32(r, addr)                                                      \
  asm volatile(                                                                 \
      "tcgen05.ld.sync.aligned.32x32b.x32.b32 "                                 \
      "{%0,%1,%2,%3,%4,%5,%6,%7,%8,%9,%10,%11,%12,%13,%14,%15,"                \
      "%16,%17,%18,%19,%20,%21,%22,%23,%24,%25,%26,%27,%28,%29,%30,%31}, [%32];" \
      : "=r"((r)[0]), "=r"((r)[1]), "=r"((r)[2]), "=r"((r)[3]),                 \
        "=r"((r)[4]), "=r"((r)[5]), "=r"((r)[6]), "=r"((r)[7]),                 \
        "=r"((r)[8]), "=r"((r)[9]), "=r"((r)[10]), "=r"((r)[11]),               \
        "=r"((r)[12]), "=r"((r)[13]), "=r"((r)[14]), "=r"((r)[15]),             \
        "=r"((r)[16]), "=r"((r)[17]), "=r"((r)[18]), "=r"((r)[19]),             \
        "=r"((r)[20]), "=r"((r)[21]), "=r"((r)[22]), "=r"((r)[23]),             \
        "=r"((r)[24]), "=r"((r)[25]), "=r"((r)[26]), "=r"((r)[27]),             \
        "=r"((r)[28]), "=r"((r)[29]), "=r"((r)[30]), "=r"((r)[31])              \
      : "r"(addr))
__device__ __forceinline__ void tc_wait_ld() {
  asm volatile("tcgen05.wait::ld.sync.aligned;" ::: "memory");
}
__device__ __forceinline__ uint64_t smem_desc_sw128(uint32_t addr) {
  const uint64_t base = (uint64_t(2) << 61) | (uint64_t(1) << 46) |
                        (uint64_t(64) << 32) | (uint64_t(1) << 16);
  return base | ((uint64_t)(addr >> 4) & 0x3FFF);
}
#endif  // HAS_TCGEN05

namespace {
constexpr uint32_t IDESC =
    (1u << 4) | (1u << 7) | (1u << 10) | ((TN / 8u) << 17) | ((128u / 16) << 24);
constexpr uint32_t IDB = (1u << 4) | (1u << 7) | (1u << 10) | (8u << 24);
constexpr uint32_t IDESC_AC = IDB | (8u << 17);    // N=64
constexpr uint32_t IDESC_G  = IDB | (24u << 17);   // N=192
constexpr uint32_t IDESC_H  = IDB | (32u << 17);   // N=256
}

// ===========================================================================
// conversions
// ===========================================================================
__global__ __launch_bounds__(256) void k_convA(const float* __restrict__ X) {
  size_t i = (size_t)blockIdx.x * 256 + threadIdx.x;
  float4 v = ((const float4*)X)[i];
  size_t m = i >> 8;
  size_t q = (i & 255) * 4;
  __nv_bfloat162 h01 = __floats2bfloat162_rn(v.x, v.y);
  __nv_bfloat162 h23 = __floats2bfloat162_rn(v.z, v.w);
  __nv_bfloat162 l01 = __floats2bfloat162_rn(v.x - __bfloat162float(h01.x),
                                             v.y - __bfloat162float(h01.y));
  __nv_bfloat162 l23 = __floats2bfloat162_rn(v.z - __bfloat162float(h23.x),
                                             v.w - __bfloat162float(h23.y));
  uint2 uh, ul;
  uh.x = *(uint32_t*)&h01; uh.y = *(uint32_t*)&h23;
  ul.x = *(uint32_t*)&l01; ul.y = *(uint32_t*)&l23;
  __nv_bfloat16* row = g_A2 + m * KTOT;
  *(uint2*)(row + q)          = uh;
  *(uint2*)(row + DM + q)     = ul;
  *(uint2*)(row + 2 * DM + q) = uh;
}

__global__ __launch_bounds__(256) void k_convB(const float* __restrict__ W) {
  __shared__ float tile[32][33];
  const int n0 = blockIdx.x * 32;
  const int k0 = blockIdx.y * 32;
  const int tid = threadIdx.x;
#pragma unroll
  for (int it = 0; it < 4; it++) {
    int e = tid + it * 256;
    tile[e >> 5][e & 31] = W[(size_t)(k0 + (e >> 5)) * QKV_N + n0 + (e & 31)];
  }
  __syncthreads();
#pragma unroll
  for (int it = 0; it < 4; it++) {
    int e = tid + it * 256;
    int nn = e >> 5, kk = e & 31;
    float x = tile[kk][nn];
    __nv_bfloat16 hi = __float2bfloat16_rn(x);
    __nv_bfloat16 lo = __float2bfloat16_rn(x - __bfloat162float(hi));
    __nv_bfloat16* row = g_B2 + (size_t)(n0 + nn) * KTOT;
    row[k0 + kk]          = hi;
    row[DM + k0 + kk]     = hi;
    row[2 * DM + k0 + kk] = lo;
  }
}

// g_qkv q/k -> pre-swizzled split bf16 (phase row&7)
__global__ __launch_bounds__(256) void k_convQK() {
  size_t e = (size_t)blockIdx.x * 256 + threadIdx.x;  // bh x qk x row x d4(16)
  int d4 = (int)(e & 15);
  int row = (int)((e >> 4) & 511);
  int qk = (int)((e >> 13) & 1);
  int bh = (int)(e >> 14);
  int b = bh >> 4, h = bh & 15;
  float4 v = *(const float4*)(g_qkv + (size_t)(b * SEQ + row) * QKV_N +
                              qk * DM + h * HD + d4 * 4);
  __nv_bfloat162 h01 = __floats2bfloat162_rn(v.x, v.y);
  __nv_bfloat162 h23 = __floats2bfloat162_rn(v.z, v.w);
  __nv_bfloat162 l01 = __floats2bfloat162_rn(v.x - __bfloat162float(h01.x),
                                             v.y - __bfloat162float(h01.y));
  __nv_bfloat162 l23 = __floats2bfloat162_rn(v.z - __bfloat162float(h23.x),
                                             v.w - __bfloat162float(h23.y));
  int pseg = (d4 >> 1) ^ (row & 7);
  unsigned char* base = (qk == 0 ? g_Q2 : g_K2) + (size_t)bh * 131072 +
                        (size_t)row * 128 + pseg * 16 + (d4 & 1) * 8;
  uint2 uh, ul;
  uh.x = *(uint32_t*)&h01; uh.y = *(uint32_t*)&h23;
  ul.x = *(uint32_t*)&l01; ul.y = *(uint32_t*)&l23;
  *(uint2*)base = uh;
  *(uint2*)(base + 65536) = ul;
}

// relpos -> g_R2 pre-swizzled split bf16, phase (t-1)&7, rows >=1024 zero
__global__ __launch_bounds__(256) void k_convR(const float* __restrict__ relpos) {
  int e = blockIdx.x * 256 + threadIdx.x;   // d4(16) x t(1040)
  if (e >= 16 * R2R) return;
  int t = e % R2R;
  int d4 = e / R2R;
  float v[4];
#pragma unroll
  for (int i = 0; i < 4; i++)
    v[i] = (t < P2) ? relpos[(size_t)(d4 * 4 + i) * P2 + t] : 0.f;
  __nv_bfloat162 h01 = __floats2bfloat162_rn(v[0], v[1]);
  __nv_bfloat162 h23 = __floats2bfloat162_rn(v[2], v[3]);
  __nv_bfloat162 l01 = __floats2bfloat162_rn(v[0] - __bfloat162float(h01.x),
                                             v[1] - __bfloat162float(h01.y));
  __nv_bfloat162 l23 = __floats2bfloat162_rn(v[2] - __bfloat162float(h23.x),
                                             v[3] - __bfloat162float(h23.y));
  int pseg = (d4 >> 1) ^ ((t - 1) & 7);
  unsigned char* base = g_R2 + (size_t)t * 128 + pseg * 16 + (d4 & 1) * 8;
  uint2 uh, ul;
  uh.x = *(uint32_t*)&h01; uh.y = *(uint32_t*)&h23;
  ul.x = *(uint32_t*)&l01; ul.y = *(uint32_t*)&l23;
  *(uint2*)base = uh;
  *(uint2*)(base + (size_t)R2R * 128) = ul;
}

// ===========================================================================
// qkv = A2 @ B2^T, 128x256 tile (R15, frozen)
// ===========================================================================
namespace {
constexpr int ASTG  = 16384;
constexpr int BSTG  = TN * CH * 2;
constexpr int QSMEM = 1024 + 2 * (ASTG + BSTG);
}

__global__ __launch_bounds__(256) void k_qkv_mma(const float* __restrict__ X,
                                                 const float* __restrict__ W) {
#if HAS_TCGEN05
  extern __shared__ char smem[];
  const uint32_t sb = smem_u32(smem);
  const uint32_t TPTR = sb, MBAR0 = sb + 16, MBAR1 = sb + 24, STAGE = sb + 1024;
  const int tid = threadIdx.x, wid = tid >> 5;

  if (wid == 0) tmem_alloc(TPTR, 256);
  if (tid == 0) { mbar_init(MBAR0, 1); mbar_init(MBAR1, 1); }
  __syncthreads();
  uint32_t tmem;
  asm volatile("ld.shared.b32 %0, [%1];" : "=r"(tmem) : "r"(TPTR));
  if (wid == 0) tmem_relinq();

  const int m0 = blockIdx.y * 128;
  const int n0 = blockIdx.x * TN;
  const __nv_bfloat16* Ag = g_A2 + (size_t)m0 * KTOT;
  const __nv_bfloat16* Bg = g_B2 + (size_t)n0 * KTOT;

  uint32_t ph0 = 0, ph1 = 0;
  for (int t = 0; t < NCH; t++) {
    const int p = t & 1;
    const uint32_t Abase = STAGE + p * (ASTG + BSTG);
    const uint32_t Bbase = Abase + ASTG;
    if (t >= 2) {
      if (p == 0) { mbar_wait(MBAR0, ph0); ph0 ^= 1; }
      else        { mbar_wait(MBAR1, ph1); ph1 ^= 1; }
    }
    const int kc = t * CH;
    uint4 av[4], bv[8];
#pragma unroll
    for (int it = 0; it < 4; it++) {
      int e = tid + it * 256;
      av[it] = *(const uint4*)((const char*)(Ag + (size_t)(e >> 3) * KTOT + kc) + (e & 7) * 16);
    }
#pragma unroll
    for (int it = 0; it < 8; it++) {
      int e = tid + it * 256;
      bv[it] = *(const uint4*)((const char*)(Bg + (size_t)(e >> 3) * KTOT + kc) + (e & 7) * 16);
    }
#pragma unroll
    for (int it = 0; it < 4; it++) {
      int e = tid + it * 256;
      uint32_t off = (e >> 3) * 128 + (e & 7) * 16;
      *(uint4*)(smem + (Abase - sb) + (off ^ ((off >> 3) & 0x70))) = av[it];
    }
#pragma unroll
    for (int it = 0; it < 8; it++) {
      int e = tid + it * 256;
      uint32_t off = (e >> 3) * 128 + (e & 7) * 16;
      *(uint4*)(smem + (Bbase - sb) + (off ^ ((off >> 3) & 0x70))) = bv[it];
    }
    __syncthreads();
    if (wid == 0 && elect_one()) {
      fence_async_shared();
      uint64_t ad = smem_desc_sw128(Abase);
      uint64_t bd = smem_desc_sw128(Bbase);
#pragma unroll
      for (int k = 0; k < 4; k++)
        mma_f16_ss(tmem, ad + k * 2, bd + k * 2, IDESC, (t > 0 || k > 0) ? 1u : 0u);
      tcommit(p == 0 ? MBAR0 : MBAR1);
    }
  }
  mbar_wait(MBAR1, ph1);
  tfence_after();

  if (wid < 4) {
    const int orow = m0 + wid * 32 + (tid & 31);
#pragma unroll
    for (int cb = 0; cb < TN; cb += 32) {
      uint32_t d[32];
      TC_LD_X32(d, tmem + cb);
      tc_wait_ld();
      float* dst = g_qkv + (size_t)orow * QKV_N + n0 + cb;
#pragma unroll
      for (int c = 0; c < 32; c += 4)
        *(float4*)(dst + c) = make_float4(__uint_as_float(d[c]),
                                          __uint_as_float(d[c + 1]),
                                          __uint_as_float(d[c + 2]),
                                          __uint_as_float(d[c + 3]));
    }
  }
  __syncthreads();
  if (wid == 0) tmem_dealloc(tmem, 256);
#else
  const int tid = threadIdx.x;
  const int m0 = blockIdx.y * 128, n0 = blockIdx.x * TN;
  for (int e = tid; e < 128 * TN; e += 256) {
    int r = m0 + e / TN, c = n0 + (e % TN);
    float s = 0.f;
    for (int k = 0; k < DM; k++) s += X[(size_t)r * DM + k] * W[(size_t)k * QKV_N + c];
    g_qkv[(size_t)r * QKV_N + c] = s;
  }
#endif
}

// ===========================================================================
// score on tcgen05: tile (bh, i0:128, j0:64)
// ===========================================================================
namespace {
constexpr int OQA = 1024;             // 2 x 128r x 128B = 32768
constexpr int OKA = OQA + 32768;      // 2 x 128r x 128B
constexpr int ORQ = OKA + 32768;      // 2 x 192r x 128B = 49152
constexpr int ORE = ORQ + 49152;      // 2 x 256r x 128B = 65536 (end 181248)
constexpr int OGS = 1024;             // 128 x 194 f32 = 99328
constexpr int OHS = OGS + 99328;      // 64 x 193 f32 = 49408
constexpr int OSS = OHS + 49408;      // 128 x 65 f32 = 33280
constexpr int SC_SMEM = OSS + 33280;  // 183040
}

__global__ __launch_bounds__(256) void k_score(const float* __restrict__ rrb,
                                               const float* __restrict__ rwb,
                                               const float* __restrict__ relpos,
                                               const float* __restrict__ prev,
                                               const int* __restrict__ skip,
                                               float* __restrict__ prev_out) {
#if HAS_TCGEN05
  extern __shared__ char smem[];
  const uint32_t sb = smem_u32(smem);
  const uint32_t TPTR = sb, MBAR = sb + 8;
  __shared__ float cK[64];
  __shared__ float cR[192];
  const int tid = threadIdx.x, wid = tid >> 5, lid = tid & 31;
  const int bh = blockIdx.z, h = bh & 15;
  const int i0 = blockIdx.y * 128;
  const int bx = blockIdx.x;
  const int j0 = bx * 64;
  const int off = (bx & 1) * 64;
  const int jB = (bx >> 1) * 128;
  const int t0q = SEQ + (j0 - i0) - 127;   // >=1, ==1 mod 8
  const int t0e = SEQ + (i0 - jB) - 127;   // >=1, ==1 mod 8

  if (wid == 0) tmem_alloc(TPTR, 512);
  if (tid == 0) mbar_init(MBAR, 1);
  __syncthreads();
  uint32_t tmem;
  asm volatile("ld.shared.b32 %0, [%1];" : "=r"(tmem) : "r"(TPTR));
  if (wid == 0) tmem_relinq();

  // raw 16B copies of pre-swizzled operands
  {
    const uint4* qg = (const uint4*)(g_Q2 + (size_t)bh * 131072);
    const uint4* kg = (const uint4*)(g_K2 + (size_t)bh * 131072);
    uint4* qa = (uint4*)(smem + OQA);
    uint4* ka = (uint4*)(smem + OKA);
#pragma unroll
    for (int it = 0; it < 8; it++) {        // ch x 128r x 8sg
      int e = tid + it * 256;
      int ch = e >> 10, r = (e >> 3) & 127, sg = e & 7;
      qa[ch * 1024 + r * 8 + sg] = qg[ch * 4096 + (i0 + r) * 8 + sg];
      ka[ch * 1024 + r * 8 + sg] = kg[ch * 4096 + (jB + r) * 8 + sg];
    }
    const uint4* rg = (const uint4*)g_R2;
    uint4* rq = (uint4*)(smem + ORQ);
    uint4* re = (uint4*)(smem + ORE);
#pragma unroll
    for (int it = 0; it < 12; it++) {       // ch x 192r x 8
      int e = tid + it * 256;
      int ch = e / 1536, rr = (e % 1536) >> 3, sg = e & 7;
      rq[ch * 1536 + rr * 8 + sg] = rg[(size_t)ch * (R2R * 8) + (t0q + rr) * 8 + sg];
    }
#pragma unroll
    for (int it = 0; it < 16; it++) {       // ch x 256r x 8
      int e = tid + it * 256;
      int ch = e >> 11, rr = (e >> 3) & 255, sg = e & 7;
      re[ch * 2048 + rr * 8 + sg] = rg[(size_t)ch * (R2R * 8) + (t0e + rr) * 8 + sg];
    }
  }
  __syncthreads();

  if (wid == 0 && elect_one()) {
    fence_async_shared();
    uint64_t qd[2] = { smem_desc_sw128(sb + OQA), smem_desc_sw128(sb + OQA + 16384) };
    uint64_t kb[2] = { smem_desc_sw128(sb + OKA + off * 128),
                       smem_desc_sw128(sb + OKA + 16384 + off * 128) };
    uint64_t ka[2] = { smem_desc_sw128(sb + OKA), smem_desc_sw128(sb + OKA + 16384) };
    uint64_t rq[2] = { smem_desc_sw128(sb + ORQ), smem_desc_sw128(sb + ORQ + 24576) };
    uint64_t re[2] = { smem_desc_sw128(sb + ORE), smem_desc_sw128(sb + ORE + 32768) };
    const int pa[3] = {0, 1, 0}, pb[3] = {0, 0, 1};
#pragma unroll
    for (int p = 0; p < 3; p++)
#pragma unroll
      for (int k = 0; k < 4; k++) {
        uint32_t en = (p > 0 || k > 0) ? 1u : 0u;
        mma_f16_ss(tmem,       qd[pa[p]] + k * 2, kb[pb[p]] + k * 2, IDESC_AC, en);
        mma_f16_ss(tmem + 64,  qd[pa[p]] + k * 2, rq[pb[p]] + k * 2, IDESC_G,  en);
        mma_f16_ss(tmem + 256, ka[pa[p]] + k * 2, re[pb[p]] + k * 2, IDESC_H,  en);
      }
    tcommit(MBAR);
  }

  // rank-1 corrections while MMAs run
  if (tid < 64) {
    int jq = off + tid;
    const unsigned char* kp = (const unsigned char*)smem + OKA + jq * 128;
    float s = 0.f;
#pragma unroll
    for (int d = 0; d < 64; d++) {
      int bo = (((d >> 3) ^ (jq & 7)) << 4) + (d & 7) * 2;
      s += rrb[h * HD + d] *
           (__bfloat162float(*(const __nv_bfloat16*)(kp + bo)) +
            __bfloat162float(*(const __nv_bfloat16*)(kp + 16384 + bo)));
    }
    cK[tid] = s;
  } else if (tid < 255) {
    int n = tid - 64;
    float s = 0.f;
#pragma unroll
    for (int d = 0; d < 64; d++)
      s += rwb[h * HD + d] * relpos[(size_t)d * P2 + t0q + n];
    cR[n] = s;
  }
  mbar_wait(MBAR, 0);
  tfence_after();
  __syncthreads();

  // stage TMEM -> smem panels (alias operand smem; operands fully consumed)
  float* Gs = (float*)(smem + OGS);       // [128][194]
  float* Hs = (float*)(smem + OHS);       // [64][193]
  float* Ss = (float*)(smem + OSS);       // [128][65]
  if (wid < 4) {
    const int il = wid * 32 + lid;
#pragma unroll
    for (int cb = 0; cb < 64; cb += 32) {
      uint32_t d[32];
      TC_LD_X32(d, tmem + cb);
      tc_wait_ld();
#pragma unroll
      for (int c = 0; c < 32; c++) Ss[il * 65 + cb + c] = __uint_as_float(d[c]);
    }
#pragma unroll
    for (int cb = 0; cb < 192; cb += 32) {
      uint32_t d[32];
      TC_LD_X32(d, tmem + 64 + cb);
      tc_wait_ld();
#pragma unroll
      for (int c = 0; c < 32; c++) Gs[il * 194 + cb + c] = __uint_as_float(d[c]);
    }
  } else {
    const int sp = wid - 4;   // subpartition sp reads lanes sp*32..
    const bool mine = (off == 0) ? (sp < 2) : (sp >= 2);
    if (mine) {
      const int jloc = (off == 0 ? sp : sp - 2) * 32 + lid;
      const int basecol = 256 + (off == 0 ? 64 : 0);
#pragma unroll
      for (int cb = 0; cb < 192; cb += 32) {
        uint32_t d[32];
        TC_LD_X32(d, tmem + basecol + cb);
        tc_wait_ld();
#pragma unroll
        for (int c = 0; c < 32; c++)
          if (cb + c < 191) Hs[jloc * 193 + cb + c] = __uint_as_float(d[c]);
      }
    }
  }
  __syncthreads();

  // gather: S = (AC + cK + G + cR + H) / 8   (in place in Ss)
  {
    const int il = (wid & 3) * 32 + lid;
    const int jb2 = (wid < 4) ? 0 : 32;
#pragma unroll 8
    for (int jj = jb2; jj < jb2 + 32; jj++) {
      int nq = jj - il + 127;               // [0,190]
      int nh = il - jj + 63;                // [0,190]
      float s = Ss[il * 65 + jj] + cK[jj] + Gs[il * 194 + nq] + cR[nq] +
                Hs[jj * 193 + nh];
      Ss[il * 65 + jj] = s * 0.125f;
    }
  }
  __syncthreads();

  // coalesced prev add + write
  const int sk = *skip;
  const float* prevb = prev + (size_t)bh * SEQ * SEQ;
  float* outb = prev_out + (size_t)bh * SEQ * SEQ;
#pragma unroll
  for (int it = 0; it < 8; it++) {
    int e = tid + it * 256;
    int r = e >> 4, c4 = (e & 15) * 4;
    float4 o = make_float4(Ss[r * 65 + c4], Ss[r * 65 + c4 + 1],
                           Ss[r * 65 + c4 + 2], Ss[r * 65 + c4 + 3]);
    if (sk) {
      float4 p = *(const float4*)(prevb + (size_t)(i0 + r) * SEQ + j0 + c4);
      o.x += p.x; o.y += p.y; o.z += p.z; o.w += p.w;
    }
    *(float4*)(outb + (size_t)(i0 + r) * SEQ + j0 + c4) = o;
  }
  __syncthreads();
  if (wid == 0) tmem_dealloc(tmem, 512);

#else  // naive fallback (non-sm_103a pass only; never runs on this chip)
  const int tid = threadIdx.x;
  const int bh = blockIdx.z, b = bh >> 4, h = bh & 15;
  const int i0 = blockIdx.y * 128, j0 = blockIdx.x * 64;
  const int sk = *skip;
  for (int e = tid; e < 128 * 64; e += 256) {
    int i = i0 + e / 64, j = j0 + (e & 63);
    const float* q = g_qkv + (size_t)(b * SEQ + i) * QKV_N + h * HD;
    const float* k = g_qkv + (size_t)(b * SEQ + j) * QKV_N + DM + h * HD;
    float s = 0.f;
    for (int d = 0; d < HD; d++)
      s += (q[d] + rrb[h * HD + d]) * k[d] +
           (q[d] + rwb[h * HD + d]) * relpos[(size_t)d * P2 + SEQ + j - i] +
           k[d] * relpos[(size_t)d * P2 + SEQ + i - j];
    s *= 0.125f;
    if (sk) s += prev[((size_t)bh * SEQ + i) * SEQ + j];
    prev_out[((size_t)bh * SEQ + i) * SEQ + j] = s;
  }
#endif
}

// ===========================================================================
// av: fused exp softmax (no max) + f32x2 PV (frozen R14/R15)
// ===========================================================================
namespace {
constexpr int ROWS_AV   = 64;
constexpr int SS_STRIDE = 516;
constexpr int SMEM_AV   = (ROWS_AV * SS_STRIDE + 64 * 64) * 4;
}

__global__ __launch_bounds__(256) void k_av(const float* __restrict__ Sglob,
                                            float* __restrict__ Out) {
#if HAS_TCGEN05
  extern __shared__ float smemf[];
  float* sS = smemf;
  float* sV = smemf + ROWS_AV * SS_STRIDE;
  __shared__ float sSum[ROWS_AV];

  const int bh = blockIdx.y, b = bh >> 4, h = bh & 15;
  const int row0 = blockIdx.x * ROWS_AV;
  const int tid = threadIdx.x;
  const int tx = tid & 15, ty = tid >> 4;
  const float* Sb = Sglob + ((size_t)bh * SEQ + row0) * SEQ;

  {
    const int warp = tid >> 5, lane = tid & 31;
#pragma unroll
    for (int rr = 0; rr < 8; rr++) {
      const int row = warp * 8 + rr;
      const float* src = Sb + (size_t)row * SEQ;
      float* srow = sS + row * SS_STRIDE;
      float sum = 0.f;
#pragma unroll
      for (int it = 0; it < 4; it++) {
        const int c = lane * 4 + it * 128;
        float4 v = *(const float4*)(src + c);
        v.x = __expf(v.x); v.y = __expf(v.y);
        v.z = __expf(v.z); v.w = __expf(v.w);
        *(float4*)&srow[c] = v;
        sum += (v.x + v.y) + (v.z + v.w);
      }
#pragma unroll
      for (int o = 16; o > 0; o >>= 1) sum += __shfl_xor_sync(0xffffffffu, sum, o);
      if (lane == 0) sSum[row] = sum;
    }
  }
  __syncthreads();

  const float* Vb = g_qkv + (size_t)(b * SEQ) * QKV_N + 2 * DM + h * HD;
  ull acc2[4][4];
#pragma unroll
  for (int r = 0; r < 4; r++)
#pragma unroll
    for (int c = 0; c < 4; c++) acc2[r][c] = 0ull;

  for (int kc = 0; kc < SEQ; kc += 64) {
    __syncthreads();
#pragma unroll
    for (int it = 0; it < 8; it++) {
      int e = tid + it * 256;
      int kp = e >> 6, c = e & 63;
      float v0 = Vb[(size_t)(kc + 2 * kp) * QKV_N + c];
      float v1 = Vb[(size_t)(kc + 2 * kp + 1) * QKV_N + c];
      *(float2*)&sV[kp * 128 + 2 * c] = make_float2(v0, v1);
    }
    __syncthreads();
#pragma unroll 8
    for (int kp = 0; kp < 32; kp++) {
      ull p2[4], v2[4];
#pragma unroll
      for (int r = 0; r < 4; r++)
        p2[r] = *(const ull*)&sS[(ty + 16 * r) * SS_STRIDE + kc + 2 * kp];
#pragma unroll
      for (int c = 0; c < 4; c++)
        v2[c] = *(const ull*)&sV[kp * 128 + (tx + 16 * c) * 2];
#pragma unroll
      for (int r = 0; r < 4; r++)
#pragma unroll
        for (int c = 0; c < 4; c++) ffma2(acc2[r][c], p2[r], v2[c]);
    }
  }

#pragma unroll
  for (int r = 0; r < 4; r++) {
    const float inv = 1.f / sSum[ty + 16 * r];
    float* dst = Out + ((size_t)b * SEQ + row0 + ty + 16 * r) * DM + h * HD + tx;
#pragma unroll
    for (int c = 0; c < 4; c++) {
      float lo = __uint_as_float((uint32_t)(acc2[r][c] & 0xffffffffull));
      float hi = __uint_as_float((uint32_t)(acc2[r][c] >> 32));
      dst[16 * c] = (lo + hi) * inv;
    }
  }
#else
  const int tid = threadIdx.x;
  const int bh = blockIdx.y, b = bh >> 4, h = bh & 15;
  const int row0 = blockIdx.x * ROWS_AV;
  for (int e = tid; e < ROWS_AV * HD; e += 256) {
    int r = row0 + e / HD, d = e % HD;
    const float* srow = Sglob + ((size_t)bh * SEQ + r) * SEQ;
    float mx = -1e30f;
    for (int k = 0; k < SEQ; k++) mx = fmaxf(mx, srow[k]);
    float sum = 0.f, acc = 0.f;
    for (int k = 0; k < SEQ; k++) {
      float p = __expf(srow[k] - mx);
      sum += p;
      acc += p * g_qkv[(size_t)(b * SEQ + k) * QKV_N + 2 * DM + h * HD + d];
    }
    Out[((size_t)b * SEQ + r) * DM + h * HD + d] = acc / sum;
  }
#endif
}

// ---------------------------------------------------------------------------
extern "C" void kernel_launch(void* const* d_in, const int* in_sizes, int n_in,
                              void* d_out, int out_size) {
  const float* x      = (const float*)d_in[0];
  const float* prev   = (const float*)d_in[1];
  const float* Wqkv   = (const float*)d_in[2];
  const float* rrb    = (const float*)d_in[3];
  const float* rwb    = (const float*)d_in[4];
  const float* relpos = (const float*)d_in[5];
  const int*   skip   = (const int*)d_in[6];

  float* out      = (float*)d_out;
  float* prev_out = out + (size_t)BATCH * SEQ * DM;

  k_convA<<<(MROWS * DM / 4) / 256, 256>>>(x);
  k_convB<<<dim3(QKV_N / 32, DM / 32), 256>>>(Wqkv);

  cudaFuncSetAttribute(k_qkv_mma, cudaFuncAttributeMaxDynamicSharedMemorySize, QSMEM);
  k_qkv_mma<<<dim3(QKV_N / TN, MROWS / 128), 256, QSMEM>>>(x, Wqkv);

  k_convQK<<<(BH * 2 * 512 * 16) / 256, 256>>>();
  k_convR<<<(16 * R2R + 255) / 256, 256>>>(relpos);

  cudaFuncSetAttribute(k_score, cudaFuncAttributeMaxDynamicSharedMemorySize, SC_SMEM);
  dim3 g3(SEQ / 64, SEQ / 128, BH);
  k_score<<<g3, 256, SC_SMEM>>>(rrb, rwb, relpos, prev, skip, prev_out);

  cudaFuncSetAttribute(k_av, cudaFuncAttributeMaxDynamicSharedMemorySize, SMEM_AV);
  dim3 g4(SEQ / ROWS_AV, BH);
  k_av<<<g4, 256, SMEM_AV>>>(prev_out, out);
}